// round 10
// baseline (speedup 1.0000x reference)
#include <cuda_runtime.h>
#include <cuda_fp16.h>
#include <math.h>
#include <cstdint>

// ---------------- problem constants ----------------
#define BSZ 8
#define RR  128
#define CC  64
#define EE  256
#define HH  8
#define HD  32
#define SPL 96
#define NT  65536
#define MHID 1024

// ---------------- scratch ----------------
__device__ float  g_Xn [(size_t)NT * EE];
__device__ float  g_X2 [(size_t)NT * EE];
__device__ float  g_X2n[(size_t)NT * EE];
__device__ __half g_QKVh[(size_t)NT * 768];
__device__ __half g_ATTh[(size_t)NT * EE];
__device__ __half g_Xnh [(size_t)NT * EE];
__device__ __half g_X2h [(size_t)NT * EE];
__device__ __half g_X2nh[(size_t)NT * EE];
__device__ __half g_Hmh [(size_t)NT * MHID];
__device__ __half g_srch[(size_t)NT * EE];
__device__ __half g_Wh  [1048576];

// weight offsets inside g_Wh
#define WOFF_YIN  0
#define WOFF_YOUT 196608
#define WOFF_XIN  262144
#define WOFF_XOUT 458752
#define WOFF_W1   524288
#define WOFF_W2   786432

// mode 0: identity; mode 1: ctx rows (r<96); mode 2: qry rows (r>=96)
__device__ __forceinline__ int maprow(int m, int mode) {
    if (mode == 1) { int b = m / 6144; return b * 8192 + (m - b * 6144); }
    if (mode == 2) { int b = m >> 11;  return b * 8192 + 6144 + (m & 2047); }
    return m;
}

__device__ __forceinline__ uint32_t smem_u32(const void* p) {
    uint32_t a;
    asm("{ .reg .u64 t; cvta.to.shared.u64 t, %1; cvt.u32.u64 %0, t; }" : "=r"(a) : "l"(p));
    return a;
}
__device__ __forceinline__ void cp_async16(uint32_t dst, const void* src) {
    asm volatile("cp.async.cg.shared.global [%0], [%1], 16;" :: "r"(dst), "l"(src));
}
#define CP_COMMIT() asm volatile("cp.async.commit_group;" ::: "memory")
#define CP_WAIT(n)  asm volatile("cp.async.wait_group %0;" :: "n"(n) : "memory")

__device__ __forceinline__ void ldsm4(uint32_t* r, uint32_t addr) {
    asm volatile("ldmatrix.sync.aligned.m8n8.x4.shared.b16 {%0,%1,%2,%3}, [%4];"
        : "=r"(r[0]), "=r"(r[1]), "=r"(r[2]), "=r"(r[3]) : "r"(addr));
}
__device__ __forceinline__ void mma_f16(float* d, const uint32_t* a, const uint32_t* b) {
    asm volatile(
        "mma.sync.aligned.m16n8k16.row.col.f32.f16.f16.f32 "
        "{%0,%1,%2,%3}, {%4,%5,%6,%7}, {%8,%9}, {%0,%1,%2,%3};"
        : "+f"(d[0]), "+f"(d[1]), "+f"(d[2]), "+f"(d[3])
        : "r"(a[0]), "r"(a[1]), "r"(a[2]), "r"(a[3]), "r"(b[0]), "r"(b[1]));
}
__device__ __forceinline__ uint32_t h2bits(float x, float y) {
    __half2 h = __floats2half2_rn(x, y);
    return *reinterpret_cast<uint32_t*>(&h);
}

// ---------------- fp16 GEMM with ldmatrix, cp.async 4-stage ----------------
// CTA 128(M) x 128(N), BK=32, 128 threads = 4 warps (2M x 2N), warp tile 64x64.
#define BKK 32
#define STAGES 4
#define ASTRH 40                      // halves per row (32 + 8 pad)
#define A_HALFS (128 * ASTRH)         // 5120
#define STAGE_HALFS (2 * A_HALFS)     // 10240
#define GEMM_SMEM (STAGES * STAGE_HALFS * 2)   // 81920 bytes

__global__ void __launch_bounds__(128, 2) gemm_mma(
    const __half* __restrict__ A, int lda,
    const __half* __restrict__ W,
    const float* __restrict__ bias,
    const float* __restrict__ Res, int ldr,
    float* __restrict__ Cm, __half* __restrict__ Ch, int ldc, int ccol,
    int M, int N, int K, int rowmap, int act, int ropeN)
{
    extern __shared__ __half smh[];
    const uint32_t smb = smem_u32(smh);

    const int tid  = threadIdx.x;
    const int wid  = tid >> 5, lane = tid & 31;
    const int g    = lane >> 2, tig = lane & 3;
    const int wm   = wid & 1,  wn  = wid >> 1;
    const int m0   = wm * 64,  n0  = wn * 64;
    const int bm   = blockIdx.y * 128, bn = blockIdx.x * 128;
    const int nbase = maprow(bm, rowmap);

    float acc[128];
    #pragma unroll
    for (int i = 0; i < 128; i++) acc[i] = 0.f;

    // cp.async coords: tiles are 128 rows x 32 halves = 64B/row = 4 chunks of 16B
    const int row0 = tid >> 2, c0 = (tid & 3) * 8;
    const __half* aP = A + (size_t)(nbase + row0) * lda + c0;
    const __half* bP = W + (size_t)(bn + row0) * K + c0;
    const uint32_t aD0 = (uint32_t)(row0 * ASTRH + c0) * 2;
    const uint32_t bD0 = aD0 + A_HALFS * 2;
    const size_t aStride = (size_t)32 * lda;
    const size_t bStride = (size_t)32 * K;

    // ldmatrix lane address bases (halves -> bytes)
    uint32_t aB[4], bB[4];
    #pragma unroll
    for (int mt = 0; mt < 4; mt++)
        aB[mt] = smb + (uint32_t)((m0 + mt * 16 + (lane & 15)) * ASTRH + (lane >> 4) * 8) * 2;
    #pragma unroll
    for (int p = 0; p < 4; p++)
        bB[p] = smb + (uint32_t)(A_HALFS
                 + (n0 + p * 16 + (lane & 7) + ((lane >> 4) & 1) * 8) * ASTRH
                 + ((lane >> 3) & 1) * 8) * 2;

    const int nk = K / BKK;

    #pragma unroll
    for (int s = 0; s < STAGES - 1; s++) {
        uint32_t sb = smb + s * (STAGE_HALFS * 2);
        int k0 = s * BKK;
        #pragma unroll
        for (int t = 0; t < 4; t++) cp_async16(sb + aD0 + t * (32 * ASTRH * 2), aP + t * aStride + k0);
        #pragma unroll
        for (int t = 0; t < 4; t++) cp_async16(sb + bD0 + t * (32 * ASTRH * 2), bP + t * bStride + k0);
        CP_COMMIT();
    }

    for (int i = 0; i < nk; i++) {
        CP_WAIT(STAGES - 2);
        __syncthreads();
        {
            int k0 = (i + STAGES - 1) * BKK;
            if (k0 < K) {
                int st = (i + STAGES - 1) % STAGES;
                uint32_t sb = smb + st * (STAGE_HALFS * 2);
                #pragma unroll
                for (int t = 0; t < 4; t++) cp_async16(sb + aD0 + t * (32 * ASTRH * 2), aP + t * aStride + k0);
                #pragma unroll
                for (int t = 0; t < 4; t++) cp_async16(sb + bD0 + t * (32 * ASTRH * 2), bP + t * bStride + k0);
            }
            CP_COMMIT();
        }
        const uint32_t stOff = (i % STAGES) * (STAGE_HALFS * 2);
        #pragma unroll
        for (int k16 = 0; k16 < 2; k16++) {
            const uint32_t kOff = stOff + k16 * 32;   // 16 halves = 32 bytes
            uint32_t af[4][4], bf[8][2];
            #pragma unroll
            for (int mt = 0; mt < 4; mt++)
                ldsm4(af[mt], aB[mt] + kOff);
            #pragma unroll
            for (int p = 0; p < 4; p++) {
                uint32_t r[4];
                ldsm4(r, bB[p] + kOff);
                bf[2 * p][0] = r[0]; bf[2 * p][1] = r[1];
                bf[2 * p + 1][0] = r[2]; bf[2 * p + 1][1] = r[3];
            }
            #pragma unroll
            for (int mt = 0; mt < 4; mt++)
                #pragma unroll
                for (int nt = 0; nt < 8; nt++)
                    mma_f16(acc + (mt * 8 + nt) * 4, af[mt], bf[nt]);
        }
    }

    // ---------------- epilogue ----------------
    #pragma unroll
    for (int mt = 0; mt < 4; mt++) {
        const int rn0 = nbase + m0 + mt * 16 + g;
        const int rn1 = rn0 + 8;
        const size_t o0 = (size_t)rn0 * ldc + ccol;
        const size_t o1 = (size_t)rn1 * ldc + ccol;
        const size_t q0 = (size_t)rn0 * ldr;
        const size_t q1 = (size_t)rn1 * ldr;
        const int r0 = (rn0 >> 6) & 127;
        const int r1 = (rn1 >> 6) & 127;
        #pragma unroll
        for (int nt = 0; nt < 8; nt++) {
            const int c = n0 + nt * 8 + 2 * tig + bn;
            const float2 bv = *reinterpret_cast<const float2*>(bias + c);
            const float* a = acc + (mt * 8 + nt) * 4;
            float v0 = a[0] + bv.x, v1 = a[1] + bv.y;
            float v2 = a[2] + bv.x, v3 = a[3] + bv.y;
            if (act == 1) {
                v0 = 0.5f * v0 * (1.f + erff(v0 * 0.70710678118654752f));
                v1 = 0.5f * v1 * (1.f + erff(v1 * 0.70710678118654752f));
                v2 = 0.5f * v2 * (1.f + erff(v2 * 0.70710678118654752f));
                v3 = 0.5f * v3 * (1.f + erff(v3 * 0.70710678118654752f));
            }
            if (c < ropeN) {
                int pi = ((ccol + c) & 31) >> 1;
                float inv = __expf(-(float)pi * 0.57564627324851148f);
                float s0, c0s, s1, c1s;
                __sincosf((float)r0 * inv, &s0, &c0s);
                __sincosf((float)r1 * inv, &s1, &c1s);
                float e0 = v0, od0 = v1, e1 = v2, od1 = v3;
                v0 = e0 * c0s - od0 * s0;  v1 = e0 * s0 + od0 * c0s;
                v2 = e1 * c1s - od1 * s1;  v3 = e1 * s1 + od1 * c1s;
            }
            if (Res) {
                const float2 rr0 = *reinterpret_cast<const float2*>(Res + q0 + c);
                const float2 rr1 = *reinterpret_cast<const float2*>(Res + q1 + c);
                v0 += rr0.x; v1 += rr0.y; v2 += rr1.x; v3 += rr1.y;
            }
            if (Cm) {
                *reinterpret_cast<float2*>(Cm + o0 + c) = make_float2(v0, v1);
                *reinterpret_cast<float2*>(Cm + o1 + c) = make_float2(v2, v3);
            }
            if (Ch) {
                uint32_t h0 = h2bits(v0, v1), h1 = h2bits(v2, v3);
                *reinterpret_cast<uint32_t*>(Ch + o0 + c) = h0;
                *reinterpret_cast<uint32_t*>(Ch + o1 + c) = h1;
            }
        }
    }
}

// ---------------- float -> half conversion (16B granules) ----------------
__global__ void f2h_kernel(const float4* __restrict__ in, uint4* __restrict__ out, int n8) {
    int i = blockIdx.x * blockDim.x + threadIdx.x;
    if (i >= n8) return;
    float4 a = in[2 * i], b = in[2 * i + 1];
    uint4 o;
    o.x = h2bits(a.x, a.y);
    o.y = h2bits(a.z, a.w);
    o.z = h2bits(b.x, b.y);
    o.w = h2bits(b.z, b.w);
    out[i] = o;
}

// ---------------- LayerNorm: warp per row, optional half copy ----------------
__global__ void __launch_bounds__(256) ln_kernel(
    const float* __restrict__ in, float* __restrict__ out, __half* __restrict__ hout,
    const float* __restrict__ g, const float* __restrict__ b)
{
    const int row  = blockIdx.x * 8 + (threadIdx.x >> 5);
    const int lane = threadIdx.x & 31;
    const float4* p = reinterpret_cast<const float4*>(in + (size_t)row * EE);
    float4 u = p[lane];
    float4 w = p[32 + lane];
    float s = (u.x + u.y) + (u.z + u.w) + (w.x + w.y) + (w.z + w.w);
    #pragma unroll
    for (int o = 16; o; o >>= 1) s += __shfl_xor_sync(0xffffffffu, s, o);
    const float mean = s * (1.0f / EE);
    u.x -= mean; u.y -= mean; u.z -= mean; u.w -= mean;
    w.x -= mean; w.y -= mean; w.z -= mean; w.w -= mean;
    float v = u.x * u.x + u.y * u.y + u.z * u.z + u.w * u.w
            + w.x * w.x + w.y * w.y + w.z * w.z + w.w * w.w;
    #pragma unroll
    for (int o = 16; o; o >>= 1) v += __shfl_xor_sync(0xffffffffu, v, o);
    const float inv = rsqrtf(v * (1.0f / EE) + 1e-5f);
    const float4 g0 = reinterpret_cast<const float4*>(g)[lane];
    const float4 g1 = reinterpret_cast<const float4*>(g)[32 + lane];
    const float4 b0 = reinterpret_cast<const float4*>(b)[lane];
    const float4 b1 = reinterpret_cast<const float4*>(b)[32 + lane];
    float4 o0, o1;
    o0.x = u.x * inv * g0.x + b0.x; o0.y = u.y * inv * g0.y + b0.y;
    o0.z = u.z * inv * g0.z + b0.z; o0.w = u.w * inv * g0.w + b0.w;
    o1.x = w.x * inv * g1.x + b1.x; o1.y = w.y * inv * g1.y + b1.y;
    o1.z = w.z * inv * g1.z + b1.z; o1.w = w.w * inv * g1.w + b1.w;
    float4* q = reinterpret_cast<float4*>(out + (size_t)row * EE);
    q[lane] = o0;
    q[32 + lane] = o1;
    if (hout) {
        uint2 h0, h1;
        h0.x = h2bits(o0.x, o0.y); h0.y = h2bits(o0.z, o0.w);
        h1.x = h2bits(o1.x, o1.y); h1.y = h2bits(o1.z, o1.w);
        uint2* hq = reinterpret_cast<uint2*>(hout + (size_t)row * EE);
        hq[lane] = h0;
        hq[32 + lane] = h1;
    }
}

// ---------------- attention: half in / half out ----------------
__global__ void __launch_bounds__(256) attn_kernel(
    const __half* __restrict__ qkv, __half* __restrict__ out,
    const int* __restrict__ mask, int Lq, int Lk, int q_r0, int modeB)
{
    int seq = blockIdx.x, head = blockIdx.y;
    int base, pstride;
    if (modeB) { base = (seq >> 6) * 8192 + (seq & 63); pstride = 64; }
    else       { base = seq * 64;                        pstride = 1;  }
    int tid = threadIdx.x;
    __shared__ float Qs[96][32];
    __shared__ float Ks[96][33];
    __shared__ float Vs[96][32];
    __shared__ float Bias[96];
    __shared__ __align__(16) float Ps[8][104];

    int qoff = head * 32, koff = 256 + head * 32, voff = 512 + head * 32;
    for (int idx = tid; idx < Lq * 4; idx += 256) {
        int rq = idx >> 2, c = idx & 3;
        uint4 raw = *reinterpret_cast<const uint4*>(
            qkv + (size_t)(base + (q_r0 + rq) * pstride) * 768 + qoff + c * 8);
        const __half2* hp = reinterpret_cast<const __half2*>(&raw);
        #pragma unroll
        for (int t = 0; t < 4; t++) {
            float2 f = __half22float2(hp[t]);
            Qs[rq][c * 8 + 2 * t]     = f.x;
            Qs[rq][c * 8 + 2 * t + 1] = f.y;
        }
    }
    for (int idx = tid; idx < Lk * 4; idx += 256) {
        int rk = idx >> 2, c = idx & 3;
        size_t rn = (size_t)(base + rk * pstride) * 768;
        uint4 kraw = *reinterpret_cast<const uint4*>(qkv + rn + koff + c * 8);
        uint4 vraw = *reinterpret_cast<const uint4*>(qkv + rn + voff + c * 8);
        const __half2* kp = reinterpret_cast<const __half2*>(&kraw);
        const __half2* vp = reinterpret_cast<const __half2*>(&vraw);
        #pragma unroll
        for (int t = 0; t < 4; t++) {
            float2 fk = __half22float2(kp[t]);
            float2 fv = __half22float2(vp[t]);
            Ks[rk][c * 8 + 2 * t]     = fk.x;
            Ks[rk][c * 8 + 2 * t + 1] = fk.y;
            Vs[rk][c * 8 + 2 * t]     = fv.x;
            Vs[rk][c * 8 + 2 * t + 1] = fv.y;
        }
    }
    if (tid < Lk) {
        float bv = 0.f;
        if (mask) { int b = seq >> 6; if (mask[b * 128 + tid] == 0) bv = -1e9f; }
        Bias[tid] = bv;
    }
    __syncthreads();

    int warp = tid >> 5, lane = tid & 31;
    const float scale = 0.17677669529663689f;
    int nk = Lk >> 5;

    for (int q = warp; q < Lq; q += 8) {
        float qreg[32];
        #pragma unroll
        for (int d = 0; d < 32; d++) qreg[d] = Qs[q][d];
        float sc[3];
        float mx = -3.4e38f;
        for (int j = 0; j < nk; j++) {
            int k = lane + (j << 5);
            float s0 = 0.f, s1 = 0.f;
            #pragma unroll
            for (int d = 0; d < 32; d += 2) {
                s0 = fmaf(qreg[d],     Ks[k][d],     s0);
                s1 = fmaf(qreg[d + 1], Ks[k][d + 1], s1);
            }
            float s = (s0 + s1) * scale + Bias[k];
            sc[j] = s;
            mx = fmaxf(mx, s);
        }
        #pragma unroll
        for (int o = 16; o; o >>= 1) mx = fmaxf(mx, __shfl_xor_sync(0xffffffffu, mx, o));
        float sum = 0.f;
        for (int j = 0; j < nk; j++) { float p = __expf(sc[j] - mx); sc[j] = p; sum += p; }
        #pragma unroll
        for (int o = 16; o; o >>= 1) sum += __shfl_xor_sync(0xffffffffu, sum, o);
        float inv = 1.f / sum;
        for (int j = 0; j < nk; j++) Ps[warp][lane + (j << 5)] = sc[j];
        __syncwarp();
        float a0 = 0.f, a1 = 0.f, a2 = 0.f, a3 = 0.f;
        for (int j = 0; j < nk; j++) {
            const int kb = j << 5;
            #pragma unroll
            for (int t = 0; t < 8; t++) {
                float4 pv = *reinterpret_cast<const float4*>(&Ps[warp][kb + t * 4]);
                a0 = fmaf(pv.x, Vs[kb + t * 4 + 0][lane], a0);
                a1 = fmaf(pv.y, Vs[kb + t * 4 + 1][lane], a1);
                a2 = fmaf(pv.z, Vs[kb + t * 4 + 2][lane], a2);
                a3 = fmaf(pv.w, Vs[kb + t * 4 + 3][lane], a3);
            }
        }
        __syncwarp();
        float accv = (a0 + a1) + (a2 + a3);
        out[(size_t)(base + (q_r0 + q) * pstride) * 256 + head * 32 + lane]
            = __float2half(accv * inv);
    }
}

// ---------------- launcher ----------------
extern "C" void kernel_launch(void* const* d_in, const int* in_sizes, int n_in,
                              void* d_out, int out_size) {
    const float* src  = (const float*)d_in[0];
    const int*   mask = (const int*)  d_in[1];
    int wi = 2;
    if (n_in > 2 && in_sizes[2] == 1) wi = 3;
    const float* y_in_w  = (const float*)d_in[wi + 0];
    const float* y_in_b  = (const float*)d_in[wi + 1];
    const float* y_out_w = (const float*)d_in[wi + 2];
    const float* y_out_b = (const float*)d_in[wi + 3];
    const float* x_in_w  = (const float*)d_in[wi + 4];
    const float* x_in_b  = (const float*)d_in[wi + 5];
    const float* x_out_w = (const float*)d_in[wi + 6];
    const float* x_out_b = (const float*)d_in[wi + 7];
    const float* w1      = (const float*)d_in[wi + 8];
    const float* b1      = (const float*)d_in[wi + 9];
    const float* w2      = (const float*)d_in[wi + 10];
    const float* b2      = (const float*)d_in[wi + 11];
    const float* n1_g    = (const float*)d_in[wi + 12];
    const float* n1_b    = (const float*)d_in[wi + 13];
    const float* n2_g    = (const float*)d_in[wi + 14];
    const float* n2_b    = (const float*)d_in[wi + 15];
    const float* n3_g    = (const float*)d_in[wi + 16];
    const float* n3_b    = (const float*)d_in[wi + 17];

    float *Xn, *X2, *X2n;
    __half *QKVh, *ATTh, *Xnh, *X2h, *X2nh, *Hmh, *srch, *Wh;
    cudaGetSymbolAddress((void**)&Xn,   g_Xn);
    cudaGetSymbolAddress((void**)&X2,   g_X2);
    cudaGetSymbolAddress((void**)&X2n,  g_X2n);
    cudaGetSymbolAddress((void**)&QKVh, g_QKVh);
    cudaGetSymbolAddress((void**)&ATTh, g_ATTh);
    cudaGetSymbolAddress((void**)&Xnh,  g_Xnh);
    cudaGetSymbolAddress((void**)&X2h,  g_X2h);
    cudaGetSymbolAddress((void**)&X2nh, g_X2nh);
    cudaGetSymbolAddress((void**)&Hmh,  g_Hmh);
    cudaGetSymbolAddress((void**)&srch, g_srch);
    cudaGetSymbolAddress((void**)&Wh,   g_Wh);

    cudaFuncSetAttribute(gemm_mma, cudaFuncAttributeMaxDynamicSharedMemorySize, GEMM_SMEM);

    // ---- conversions (src + weights) ----
    f2h_kernel<<<(NT * EE / 8 + 255) / 256, 256>>>((const float4*)src, (uint4*)srch, NT * EE / 8);
    f2h_kernel<<<(196608 / 8 + 255) / 256, 256>>>((const float4*)y_in_w,  (uint4*)(Wh + WOFF_YIN),  196608 / 8);
    f2h_kernel<<<(65536  / 8 + 255) / 256, 256>>>((const float4*)y_out_w, (uint4*)(Wh + WOFF_YOUT), 65536 / 8);
    f2h_kernel<<<(196608 / 8 + 255) / 256, 256>>>((const float4*)x_in_w,  (uint4*)(Wh + WOFF_XIN),  196608 / 8);
    f2h_kernel<<<(65536  / 8 + 255) / 256, 256>>>((const float4*)x_out_w, (uint4*)(Wh + WOFF_XOUT), 65536 / 8);
    f2h_kernel<<<(262144 / 8 + 255) / 256, 256>>>((const float4*)w1,      (uint4*)(Wh + WOFF_W1),   262144 / 8);
    f2h_kernel<<<(262144 / 8 + 255) / 256, 256>>>((const float4*)w2,      (uint4*)(Wh + WOFF_W2),   262144 / 8);

    // ---- stage A ----
    gemm_mma<<<dim3(6, 512), 128, GEMM_SMEM>>>(srch, 256, Wh + WOFF_YIN, y_in_b, nullptr, 0,
                                               nullptr, QKVh, 768, 0, NT, 768, 256, 0, 0, 0);
    attn_kernel<<<dim3(1024, HH), 256>>>(QKVh, ATTh, nullptr, 64, 64, 0, 0);
    gemm_mma<<<dim3(2, 512), 128, GEMM_SMEM>>>(ATTh, 256, Wh + WOFF_YOUT, y_out_b, src, 256,
                                               X2, nullptr, 256, 0, NT, 256, 256, 0, 0, 0);
    ln_kernel<<<NT / 8, 256>>>(X2, Xn, Xnh, n1_g, n1_b);

    // ---- stage B ----
    gemm_mma<<<dim3(6, 384), 128, GEMM_SMEM>>>(Xnh, 256, Wh + WOFF_XIN, x_in_b, nullptr, 0,
                                               nullptr, QKVh, 768, 0, 49152, 768, 256, 1, 0, 512);
    gemm_mma<<<dim3(2, 128), 128, GEMM_SMEM>>>(Xnh, 256, Wh + WOFF_XIN, x_in_b, nullptr, 0,
                                               nullptr, QKVh, 768, 0, 16384, 256, 256, 2, 0, 256);
    attn_kernel<<<dim3(512, HH), 256>>>(QKVh, ATTh, mask, 96, 96, 0, 1);
    gemm_mma<<<dim3(2, 384), 128, GEMM_SMEM>>>(ATTh, 256, Wh + WOFF_XOUT, x_out_b, Xn, 256,
                                               X2, X2h, 256, 0, 49152, 256, 256, 1, 0, 0);
    gemm_mma<<<dim3(4, 384), 128, GEMM_SMEM>>>(X2h, 256, Wh + WOFF_XIN + 65536, x_in_b + 256,
                                               nullptr, 0, nullptr, QKVh, 768, 256,
                                               49152, 512, 256, 1, 0, 256);
    attn_kernel<<<dim3(512, HH), 256>>>(QKVh, ATTh, mask, 32, 96, 96, 1);
    gemm_mma<<<dim3(2, 128), 128, GEMM_SMEM>>>(ATTh, 256, Wh + WOFF_XOUT, x_out_b, Xn, 256,
                                               X2, nullptr, 256, 0, 16384, 256, 256, 2, 0, 0);
    ln_kernel<<<NT / 8, 256>>>(X2, X2n, X2nh, n2_g, n2_b);

    // ---- MLP + final LN ----
    gemm_mma<<<dim3(8, 512), 128, GEMM_SMEM>>>(X2nh, 256, Wh + WOFF_W1, b1, nullptr, 0,
                                               nullptr, Hmh, 1024, 0, NT, 1024, 256, 0, 1, 0);
    gemm_mma<<<dim3(2, 512), 128, GEMM_SMEM>>>(Hmh, 1024, Wh + WOFF_W2, b2, X2n, 256,
                                               X2, nullptr, 256, 0, NT, 256, 1024, 0, 0, 0);
    ln_kernel<<<NT / 8, 256>>>(X2, (float*)d_out, nullptr, n3_g, n3_b);
}

// round 11
// speedup vs baseline: 1.0002x; 1.0002x over previous
#include <cuda_runtime.h>
#include <cuda_fp16.h>
#include <math.h>
#include <cstdint>

// ---------------- problem constants ----------------
#define BSZ 8
#define RR  128
#define CC  64
#define EE  256
#define HH  8
#define HD  32
#define SPL 96
#define NT  65536
#define MHID 1024

// ---------------- scratch ----------------
__device__ float  g_Xn [(size_t)NT * EE];
__device__ float  g_X2 [(size_t)NT * EE];
__device__ float  g_X2n[(size_t)NT * EE];
__device__ __half g_QKVh[(size_t)NT * 768];
__device__ __half g_ATTh[(size_t)NT * EE];
__device__ __half g_Xnh [(size_t)NT * EE];
__device__ __half g_X2h [(size_t)NT * EE];
__device__ __half g_X2nh[(size_t)NT * EE];
__device__ __half g_Hmh [(size_t)NT * MHID];
__device__ __half g_srch[(size_t)NT * EE];
__device__ __half g_Wh  [1048576];

// weight offsets inside g_Wh
#define WOFF_YIN  0
#define WOFF_YOUT 196608
#define WOFF_XIN  262144
#define WOFF_XOUT 458752
#define WOFF_W1   524288
#define WOFF_W2   786432

// mode 0: identity; mode 1: ctx rows (r<96); mode 2: qry rows (r>=96)
__device__ __forceinline__ int maprow(int m, int mode) {
    if (mode == 1) { int b = m / 6144; return b * 8192 + (m - b * 6144); }
    if (mode == 2) { int b = m >> 11;  return b * 8192 + 6144 + (m & 2047); }
    return m;
}

__device__ __forceinline__ uint32_t smem_u32(const void* p) {
    uint32_t a;
    asm("{ .reg .u64 t; cvta.to.shared.u64 t, %1; cvt.u32.u64 %0, t; }" : "=r"(a) : "l"(p));
    return a;
}
__device__ __forceinline__ void cp_async16(uint32_t dst, const void* src) {
    asm volatile("cp.async.cg.shared.global [%0], [%1], 16;" :: "r"(dst), "l"(src));
}
#define CP_COMMIT() asm volatile("cp.async.commit_group;" ::: "memory")
#define CP_WAIT(n)  asm volatile("cp.async.wait_group %0;" :: "n"(n) : "memory")

__device__ __forceinline__ void ldsm4(uint32_t* r, uint32_t addr) {
    asm volatile("ldmatrix.sync.aligned.m8n8.x4.shared.b16 {%0,%1,%2,%3}, [%4];"
        : "=r"(r[0]), "=r"(r[1]), "=r"(r[2]), "=r"(r[3]) : "r"(addr));
}
__device__ __forceinline__ void mma_f16(float* d, const uint32_t* a, const uint32_t* b) {
    asm volatile(
        "mma.sync.aligned.m16n8k16.row.col.f32.f16.f16.f32 "
        "{%0,%1,%2,%3}, {%4,%5,%6,%7}, {%8,%9}, {%0,%1,%2,%3};"
        : "+f"(d[0]), "+f"(d[1]), "+f"(d[2]), "+f"(d[3])
        : "r"(a[0]), "r"(a[1]), "r"(a[2]), "r"(a[3]), "r"(b[0]), "r"(b[1]));
}
__device__ __forceinline__ uint32_t h2bits(float x, float y) {
    __half2 h = __floats2half2_rn(x, y);
    return *reinterpret_cast<uint32_t*>(&h);
}

// ---------------- fp16 GEMM with ldmatrix, cp.async 4-stage ----------------
// CTA 128(M) x 128(N), BK=32, 128 threads = 4 warps (2M x 2N), warp tile 64x64.
#define BKK 32
#define STAGES 4
#define ASTRH 40                      // halves per row (32 + 8 pad)
#define A_HALFS (128 * ASTRH)         // 5120
#define STAGE_HALFS (2 * A_HALFS)     // 10240
#define GEMM_SMEM (STAGES * STAGE_HALFS * 2)   // 81920 bytes

__global__ void __launch_bounds__(128, 2) gemm_mma(
    const __half* __restrict__ A, int lda,
    const __half* __restrict__ W,
    const float* __restrict__ bias,
    const float* __restrict__ Res, int ldr,
    float* __restrict__ Cm, __half* __restrict__ Ch, int ldc, int ccol,
    int M, int N, int K, int rowmap, int act, int ropeN)
{
    extern __shared__ __half smh[];
    const uint32_t smb = smem_u32(smh);

    const int tid  = threadIdx.x;
    const int wid  = tid >> 5, lane = tid & 31;
    const int g    = lane >> 2, tig = lane & 3;
    const int wm   = wid & 1,  wn  = wid >> 1;
    const int m0   = wm * 64,  n0  = wn * 64;
    const int bm   = blockIdx.y * 128, bn = blockIdx.x * 128;
    const int nbase = maprow(bm, rowmap);

    float acc[128];
    #pragma unroll
    for (int i = 0; i < 128; i++) acc[i] = 0.f;

    // cp.async coords: tiles are 128 rows x 32 halves = 64B/row = 4 chunks of 16B
    const int row0 = tid >> 2, c0 = (tid & 3) * 8;
    const __half* aP = A + (size_t)(nbase + row0) * lda + c0;
    const __half* bP = W + (size_t)(bn + row0) * K + c0;
    const uint32_t aD0 = (uint32_t)(row0 * ASTRH + c0) * 2;
    const uint32_t bD0 = aD0 + A_HALFS * 2;
    const size_t aStride = (size_t)32 * lda;
    const size_t bStride = (size_t)32 * K;

    // ldmatrix lane address bases (halves -> bytes)
    uint32_t aB[4], bB[4];
    #pragma unroll
    for (int mt = 0; mt < 4; mt++)
        aB[mt] = smb + (uint32_t)((m0 + mt * 16 + (lane & 15)) * ASTRH + (lane >> 4) * 8) * 2;
    #pragma unroll
    for (int p = 0; p < 4; p++)
        bB[p] = smb + (uint32_t)(A_HALFS
                 + (n0 + p * 16 + (lane & 7) + ((lane >> 4) & 1) * 8) * ASTRH
                 + ((lane >> 3) & 1) * 8) * 2;

    const int nk = K / BKK;

    #pragma unroll
    for (int s = 0; s < STAGES - 1; s++) {
        uint32_t sb = smb + s * (STAGE_HALFS * 2);
        int k0 = s * BKK;
        #pragma unroll
        for (int t = 0; t < 4; t++) cp_async16(sb + aD0 + t * (32 * ASTRH * 2), aP + t * aStride + k0);
        #pragma unroll
        for (int t = 0; t < 4; t++) cp_async16(sb + bD0 + t * (32 * ASTRH * 2), bP + t * bStride + k0);
        CP_COMMIT();
    }

    for (int i = 0; i < nk; i++) {
        CP_WAIT(STAGES - 2);
        __syncthreads();
        {
            int k0 = (i + STAGES - 1) * BKK;
            if (k0 < K) {
                int st = (i + STAGES - 1) % STAGES;
                uint32_t sb = smb + st * (STAGE_HALFS * 2);
                #pragma unroll
                for (int t = 0; t < 4; t++) cp_async16(sb + aD0 + t * (32 * ASTRH * 2), aP + t * aStride + k0);
                #pragma unroll
                for (int t = 0; t < 4; t++) cp_async16(sb + bD0 + t * (32 * ASTRH * 2), bP + t * bStride + k0);
            }
            CP_COMMIT();
        }
        const uint32_t stOff = (i % STAGES) * (STAGE_HALFS * 2);
        #pragma unroll
        for (int k16 = 0; k16 < 2; k16++) {
            const uint32_t kOff = stOff + k16 * 32;   // 16 halves = 32 bytes
            uint32_t af[4][4], bf[8][2];
            #pragma unroll
            for (int mt = 0; mt < 4; mt++)
                ldsm4(af[mt], aB[mt] + kOff);
            #pragma unroll
            for (int p = 0; p < 4; p++) {
                uint32_t r[4];
                ldsm4(r, bB[p] + kOff);
                bf[2 * p][0] = r[0]; bf[2 * p][1] = r[1];
                bf[2 * p + 1][0] = r[2]; bf[2 * p + 1][1] = r[3];
            }
            #pragma unroll
            for (int mt = 0; mt < 4; mt++)
                #pragma unroll
                for (int nt = 0; nt < 8; nt++)
                    mma_f16(acc + (mt * 8 + nt) * 4, af[mt], bf[nt]);
        }
    }

    // ---------------- epilogue ----------------
    #pragma unroll
    for (int mt = 0; mt < 4; mt++) {
        const int rn0 = nbase + m0 + mt * 16 + g;
        const int rn1 = rn0 + 8;
        const size_t o0 = (size_t)rn0 * ldc + ccol;
        const size_t o1 = (size_t)rn1 * ldc + ccol;
        const size_t q0 = (size_t)rn0 * ldr;
        const size_t q1 = (size_t)rn1 * ldr;
        const int r0 = (rn0 >> 6) & 127;
        const int r1 = (rn1 >> 6) & 127;
        #pragma unroll
        for (int nt = 0; nt < 8; nt++) {
            const int c = n0 + nt * 8 + 2 * tig + bn;
            const float2 bv = *reinterpret_cast<const float2*>(bias + c);
            const float* a = acc + (mt * 8 + nt) * 4;
            float v0 = a[0] + bv.x, v1 = a[1] + bv.y;
            float v2 = a[2] + bv.x, v3 = a[3] + bv.y;
            if (act == 1) {
                v0 = 0.5f * v0 * (1.f + erff(v0 * 0.70710678118654752f));
                v1 = 0.5f * v1 * (1.f + erff(v1 * 0.70710678118654752f));
                v2 = 0.5f * v2 * (1.f + erff(v2 * 0.70710678118654752f));
                v3 = 0.5f * v3 * (1.f + erff(v3 * 0.70710678118654752f));
            }
            if (c < ropeN) {
                int pi = ((ccol + c) & 31) >> 1;
                float inv = __expf(-(float)pi * 0.57564627324851148f);
                float s0, c0s, s1, c1s;
                __sincosf((float)r0 * inv, &s0, &c0s);
                __sincosf((float)r1 * inv, &s1, &c1s);
                float e0 = v0, od0 = v1, e1 = v2, od1 = v3;
                v0 = e0 * c0s - od0 * s0;  v1 = e0 * s0 + od0 * c0s;
                v2 = e1 * c1s - od1 * s1;  v3 = e1 * s1 + od1 * c1s;
            }
            if (Res) {
                const float2 rr0 = *reinterpret_cast<const float2*>(Res + q0 + c);
                const float2 rr1 = *reinterpret_cast<const float2*>(Res + q1 + c);
                v0 += rr0.x; v1 += rr0.y; v2 += rr1.x; v3 += rr1.y;
            }
            if (Cm) {
                *reinterpret_cast<float2*>(Cm + o0 + c) = make_float2(v0, v1);
                *reinterpret_cast<float2*>(Cm + o1 + c) = make_float2(v2, v3);
            }
            if (Ch) {
                uint32_t h0 = h2bits(v0, v1), h1 = h2bits(v2, v3);
                *reinterpret_cast<uint32_t*>(Ch + o0 + c) = h0;
                *reinterpret_cast<uint32_t*>(Ch + o1 + c) = h1;
            }
        }
    }
}

// ---------------- float -> half conversion (16B granules) ----------------
__global__ void f2h_kernel(const float4* __restrict__ in, uint4* __restrict__ out, int n8) {
    int i = blockIdx.x * blockDim.x + threadIdx.x;
    if (i >= n8) return;
    float4 a = in[2 * i], b = in[2 * i + 1];
    uint4 o;
    o.x = h2bits(a.x, a.y);
    o.y = h2bits(a.z, a.w);
    o.z = h2bits(b.x, b.y);
    o.w = h2bits(b.z, b.w);
    out[i] = o;
}

// ---------------- LayerNorm: warp per row, optional half copy ----------------
__global__ void __launch_bounds__(256) ln_kernel(
    const float* __restrict__ in, float* __restrict__ out, __half* __restrict__ hout,
    const float* __restrict__ g, const float* __restrict__ b)
{
    const int row  = blockIdx.x * 8 + (threadIdx.x >> 5);
    const int lane = threadIdx.x & 31;
    const float4* p = reinterpret_cast<const float4*>(in + (size_t)row * EE);
    float4 u = p[lane];
    float4 w = p[32 + lane];
    float s = (u.x + u.y) + (u.z + u.w) + (w.x + w.y) + (w.z + w.w);
    #pragma unroll
    for (int o = 16; o; o >>= 1) s += __shfl_xor_sync(0xffffffffu, s, o);
    const float mean = s * (1.0f / EE);
    u.x -= mean; u.y -= mean; u.z -= mean; u.w -= mean;
    w.x -= mean; w.y -= mean; w.z -= mean; w.w -= mean;
    float v = u.x * u.x + u.y * u.y + u.z * u.z + u.w * u.w
            + w.x * w.x + w.y * w.y + w.z * w.z + w.w * w.w;
    #pragma unroll
    for (int o = 16; o; o >>= 1) v += __shfl_xor_sync(0xffffffffu, v, o);
    const float inv = rsqrtf(v * (1.0f / EE) + 1e-5f);
    const float4 g0 = reinterpret_cast<const float4*>(g)[lane];
    const float4 g1 = reinterpret_cast<const float4*>(g)[32 + lane];
    const float4 b0 = reinterpret_cast<const float4*>(b)[lane];
    const float4 b1 = reinterpret_cast<const float4*>(b)[32 + lane];
    float4 o0, o1;
    o0.x = u.x * inv * g0.x + b0.x; o0.y = u.y * inv * g0.y + b0.y;
    o0.z = u.z * inv * g0.z + b0.z; o0.w = u.w * inv * g0.w + b0.w;
    o1.x = w.x * inv * g1.x + b1.x; o1.y = w.y * inv * g1.y + b1.y;
    o1.z = w.z * inv * g1.z + b1.z; o1.w = w.w * inv * g1.w + b1.w;
    float4* q = reinterpret_cast<float4*>(out + (size_t)row * EE);
    q[lane] = o0;
    q[32 + lane] = o1;
    if (hout) {
        uint2 h0, h1;
        h0.x = h2bits(o0.x, o0.y); h0.y = h2bits(o0.z, o0.w);
        h1.x = h2bits(o1.x, o1.y); h1.y = h2bits(o1.z, o1.w);
        uint2* hq = reinterpret_cast<uint2*>(hout + (size_t)row * EE);
        hq[lane] = h0;
        hq[32 + lane] = h1;
    }
}

// ---------------- attention: half in / half out ----------------
__global__ void __launch_bounds__(256) attn_kernel(
    const __half* __restrict__ qkv, __half* __restrict__ out,
    const int* __restrict__ mask, int Lq, int Lk, int q_r0, int modeB)
{
    int seq = blockIdx.x, head = blockIdx.y;
    int base, pstride;
    if (modeB) { base = (seq >> 6) * 8192 + (seq & 63); pstride = 64; }
    else       { base = seq * 64;                        pstride = 1;  }
    int tid = threadIdx.x;
    __shared__ float Qs[96][32];
    __shared__ float Ks[96][33];
    __shared__ float Vs[96][32];
    __shared__ float Bias[96];
    __shared__ __align__(16) float Ps[8][104];

    int qoff = head * 32, koff = 256 + head * 32, voff = 512 + head * 32;
    for (int idx = tid; idx < Lq * 4; idx += 256) {
        int rq = idx >> 2, c = idx & 3;
        uint4 raw = *reinterpret_cast<const uint4*>(
            qkv + (size_t)(base + (q_r0 + rq) * pstride) * 768 + qoff + c * 8);
        const __half2* hp = reinterpret_cast<const __half2*>(&raw);
        #pragma unroll
        for (int t = 0; t < 4; t++) {
            float2 f = __half22float2(hp[t]);
            Qs[rq][c * 8 + 2 * t]     = f.x;
            Qs[rq][c * 8 + 2 * t + 1] = f.y;
        }
    }
    for (int idx = tid; idx < Lk * 4; idx += 256) {
        int rk = idx >> 2, c = idx & 3;
        size_t rn = (size_t)(base + rk * pstride) * 768;
        uint4 kraw = *reinterpret_cast<const uint4*>(qkv + rn + koff + c * 8);
        uint4 vraw = *reinterpret_cast<const uint4*>(qkv + rn + voff + c * 8);
        const __half2* kp = reinterpret_cast<const __half2*>(&kraw);
        const __half2* vp = reinterpret_cast<const __half2*>(&vraw);
        #pragma unroll
        for (int t = 0; t < 4; t++) {
            float2 fk = __half22float2(kp[t]);
            float2 fv = __half22float2(vp[t]);
            Ks[rk][c * 8 + 2 * t]     = fk.x;
            Ks[rk][c * 8 + 2 * t + 1] = fk.y;
            Vs[rk][c * 8 + 2 * t]     = fv.x;
            Vs[rk][c * 8 + 2 * t + 1] = fv.y;
        }
    }
    if (tid < Lk) {
        float bv = 0.f;
        if (mask) { int b = seq >> 6; if (mask[b * 128 + tid] == 0) bv = -1e9f; }
        Bias[tid] = bv;
    }
    __syncthreads();

    int warp = tid >> 5, lane = tid & 31;
    const float scale = 0.17677669529663689f;
    int nk = Lk >> 5;

    for (int q = warp; q < Lq; q += 8) {
        float qreg[32];
        #pragma unroll
        for (int d = 0; d < 32; d++) qreg[d] = Qs[q][d];
        float sc[3];
        float mx = -3.4e38f;
        for (int j = 0; j < nk; j++) {
            int k = lane + (j << 5);
            float s0 = 0.f, s1 = 0.f;
            #pragma unroll
            for (int d = 0; d < 32; d += 2) {
                s0 = fmaf(qreg[d],     Ks[k][d],     s0);
                s1 = fmaf(qreg[d + 1], Ks[k][d + 1], s1);
            }
            float s = (s0 + s1) * scale + Bias[k];
            sc[j] = s;
            mx = fmaxf(mx, s);
        }
        #pragma unroll
        for (int o = 16; o; o >>= 1) mx = fmaxf(mx, __shfl_xor_sync(0xffffffffu, mx, o));
        float sum = 0.f;
        for (int j = 0; j < nk; j++) { float p = __expf(sc[j] - mx); sc[j] = p; sum += p; }
        #pragma unroll
        for (int o = 16; o; o >>= 1) sum += __shfl_xor_sync(0xffffffffu, sum, o);
        float inv = 1.f / sum;
        for (int j = 0; j < nk; j++) Ps[warp][lane + (j << 5)] = sc[j];
        __syncwarp();
        float a0 = 0.f, a1 = 0.f, a2 = 0.f, a3 = 0.f;
        for (int j = 0; j < nk; j++) {
            const int kb = j << 5;
            #pragma unroll
            for (int t = 0; t < 8; t++) {
                float4 pv = *reinterpret_cast<const float4*>(&Ps[warp][kb + t * 4]);
                a0 = fmaf(pv.x, Vs[kb + t * 4 + 0][lane], a0);
                a1 = fmaf(pv.y, Vs[kb + t * 4 + 1][lane], a1);
                a2 = fmaf(pv.z, Vs[kb + t * 4 + 2][lane], a2);
                a3 = fmaf(pv.w, Vs[kb + t * 4 + 3][lane], a3);
            }
        }
        __syncwarp();
        float accv = (a0 + a1) + (a2 + a3);
        out[(size_t)(base + (q_r0 + q) * pstride) * 256 + head * 32 + lane]
            = __float2half(accv * inv);
    }
}

// ---------------- launcher ----------------
extern "C" void kernel_launch(void* const* d_in, const int* in_sizes, int n_in,
                              void* d_out, int out_size) {
    const float* src  = (const float*)d_in[0];
    const int*   mask = (const int*)  d_in[1];
    int wi = 2;
    if (n_in > 2 && in_sizes[2] == 1) wi = 3;
    const float* y_in_w  = (const float*)d_in[wi + 0];
    const float* y_in_b  = (const float*)d_in[wi + 1];
    const float* y_out_w = (const float*)d_in[wi + 2];
    const float* y_out_b = (const float*)d_in[wi + 3];
    const float* x_in_w  = (const float*)d_in[wi + 4];
    const float* x_in_b  = (const float*)d_in[wi + 5];
    const float* x_out_w = (const float*)d_in[wi + 6];
    const float* x_out_b = (const float*)d_in[wi + 7];
    const float* w1      = (const float*)d_in[wi + 8];
    const float* b1      = (const float*)d_in[wi + 9];
    const float* w2      = (const float*)d_in[wi + 10];
    const float* b2      = (const float*)d_in[wi + 11];
    const float* n1_g    = (const float*)d_in[wi + 12];
    const float* n1_b    = (const float*)d_in[wi + 13];
    const float* n2_g    = (const float*)d_in[wi + 14];
    const float* n2_b    = (const float*)d_in[wi + 15];
    const float* n3_g    = (const float*)d_in[wi + 16];
    const float* n3_b    = (const float*)d_in[wi + 17];

    float *Xn, *X2, *X2n;
    __half *QKVh, *ATTh, *Xnh, *X2h, *X2nh, *Hmh, *srch, *Wh;
    cudaGetSymbolAddress((void**)&Xn,   g_Xn);
    cudaGetSymbolAddress((void**)&X2,   g_X2);
    cudaGetSymbolAddress((void**)&X2n,  g_X2n);
    cudaGetSymbolAddress((void**)&QKVh, g_QKVh);
    cudaGetSymbolAddress((void**)&ATTh, g_ATTh);
    cudaGetSymbolAddress((void**)&Xnh,  g_Xnh);
    cudaGetSymbolAddress((void**)&X2h,  g_X2h);
    cudaGetSymbolAddress((void**)&X2nh, g_X2nh);
    cudaGetSymbolAddress((void**)&Hmh,  g_Hmh);
    cudaGetSymbolAddress((void**)&srch, g_srch);
    cudaGetSymbolAddress((void**)&Wh,   g_Wh);

    cudaFuncSetAttribute(gemm_mma, cudaFuncAttributeMaxDynamicSharedMemorySize, GEMM_SMEM);

    // ---- conversions (src + weights) ----
    f2h_kernel<<<(NT * EE / 8 + 255) / 256, 256>>>((const float4*)src, (uint4*)srch, NT * EE / 8);
    f2h_kernel<<<(196608 / 8 + 255) / 256, 256>>>((const float4*)y_in_w,  (uint4*)(Wh + WOFF_YIN),  196608 / 8);
    f2h_kernel<<<(65536  / 8 + 255) / 256, 256>>>((const float4*)y_out_w, (uint4*)(Wh + WOFF_YOUT), 65536 / 8);
    f2h_kernel<<<(196608 / 8 + 255) / 256, 256>>>((const float4*)x_in_w,  (uint4*)(Wh + WOFF_XIN),  196608 / 8);
    f2h_kernel<<<(65536  / 8 + 255) / 256, 256>>>((const float4*)x_out_w, (uint4*)(Wh + WOFF_XOUT), 65536 / 8);
    f2h_kernel<<<(262144 / 8 + 255) / 256, 256>>>((const float4*)w1,      (uint4*)(Wh + WOFF_W1),   262144 / 8);
    f2h_kernel<<<(262144 / 8 + 255) / 256, 256>>>((const float4*)w2,      (uint4*)(Wh + WOFF_W2),   262144 / 8);

    // ---- stage A ----
    gemm_mma<<<dim3(6, 512), 128, GEMM_SMEM>>>(srch, 256, Wh + WOFF_YIN, y_in_b, nullptr, 0,
                                               nullptr, QKVh, 768, 0, NT, 768, 256, 0, 0, 0);
    attn_kernel<<<dim3(1024, HH), 256>>>(QKVh, ATTh, nullptr, 64, 64, 0, 0);
    gemm_mma<<<dim3(2, 512), 128, GEMM_SMEM>>>(ATTh, 256, Wh + WOFF_YOUT, y_out_b, src, 256,
                                               X2, nullptr, 256, 0, NT, 256, 256, 0, 0, 0);
    ln_kernel<<<NT / 8, 256>>>(X2, Xn, Xnh, n1_g, n1_b);

    // ---- stage B ----
    gemm_mma<<<dim3(6, 384), 128, GEMM_SMEM>>>(Xnh, 256, Wh + WOFF_XIN, x_in_b, nullptr, 0,
                                               nullptr, QKVh, 768, 0, 49152, 768, 256, 1, 0, 512);
    gemm_mma<<<dim3(2, 128), 128, GEMM_SMEM>>>(Xnh, 256, Wh + WOFF_XIN, x_in_b, nullptr, 0,
                                               nullptr, QKVh, 768, 0, 16384, 256, 256, 2, 0, 256);
    attn_kernel<<<dim3(512, HH), 256>>>(QKVh, ATTh, mask, 96, 96, 0, 1);
    gemm_mma<<<dim3(2, 384), 128, GEMM_SMEM>>>(ATTh, 256, Wh + WOFF_XOUT, x_out_b, Xn, 256,
                                               X2, X2h, 256, 0, 49152, 256, 256, 1, 0, 0);
    gemm_mma<<<dim3(4, 384), 128, GEMM_SMEM>>>(X2h, 256, Wh + WOFF_XIN + 65536, x_in_b + 256,
                                               nullptr, 0, nullptr, QKVh, 768, 256,
                                               49152, 512, 256, 1, 0, 256);
    attn_kernel<<<dim3(512, HH), 256>>>(QKVh, ATTh, mask, 32, 96, 96, 1);
    gemm_mma<<<dim3(2, 128), 128, GEMM_SMEM>>>(ATTh, 256, Wh + WOFF_XOUT, x_out_b, Xn, 256,
                                               X2, nullptr, 256, 0, 16384, 256, 256, 2, 0, 0);
    ln_kernel<<<NT / 8, 256>>>(X2, X2n, X2nh, n2_g, n2_b);

    // ---- MLP + final LN ----
    gemm_mma<<<dim3(8, 512), 128, GEMM_SMEM>>>(X2nh, 256, Wh + WOFF_W1, b1, nullptr, 0,
                                               nullptr, Hmh, 1024, 0, NT, 1024, 256, 0, 1, 0);
    gemm_mma<<<dim3(2, 512), 128, GEMM_SMEM>>>(Hmh, 1024, Wh + WOFF_W2, b2, X2n, 256,
                                               X2, nullptr, 256, 0, NT, 256, 1024, 0, 0, 0);
    ln_kernel<<<NT / 8, 256>>>(X2, (float*)d_out, nullptr, n3_g, n3_b);
}

// round 13
// speedup vs baseline: 1.8636x; 1.8633x over previous
#include <cuda_runtime.h>
#include <cuda_fp16.h>
#include <math.h>
#include <cstdint>

// ---------------- problem constants ----------------
#define BSZ 8
#define RR  128
#define CC  64
#define EE  256
#define HH  8
#define HD  32
#define SPL 96
#define NT  65536
#define MHID 1024

// ---------------- scratch ----------------
__device__ float  g_Xn [(size_t)NT * EE];
__device__ float  g_X2 [(size_t)NT * EE];
__device__ float  g_X2n[(size_t)NT * EE];
__device__ __half g_QKVh[(size_t)NT * 768];
__device__ __half g_ATTh[(size_t)NT * EE];
__device__ __half g_Xnh [(size_t)NT * EE];
__device__ __half g_X2h [(size_t)NT * EE];
__device__ __half g_X2nh[(size_t)NT * EE];
__device__ __half g_Hmh [(size_t)NT * MHID];
__device__ __half g_srch[(size_t)NT * EE];
__device__ __half g_Wh  [1048576];

#define WOFF_YIN  0
#define WOFF_YOUT 196608
#define WOFF_XIN  262144
#define WOFF_XOUT 458752
#define WOFF_W1   524288
#define WOFF_W2   786432

// mode 0: identity; mode 1: ctx rows (r<96); mode 2: qry rows (r>=96)
__device__ __forceinline__ int maprow(int m, int mode) {
    if (mode == 1) { int b = m / 6144; return b * 8192 + (m - b * 6144); }
    if (mode == 2) { int b = m >> 11;  return b * 8192 + 6144 + (m & 2047); }
    return m;
}

__device__ __forceinline__ uint32_t smem_u32(const void* p) {
    uint32_t a;
    asm("{ .reg .u64 t; cvta.to.shared.u64 t, %1; cvt.u32.u64 %0, t; }" : "=r"(a) : "l"(p));
    return a;
}
__device__ __forceinline__ void cp_async16(uint32_t dst, const void* src) {
    asm volatile("cp.async.cg.shared.global [%0], [%1], 16;" :: "r"(dst), "l"(src));
}
#define CP_COMMIT() asm volatile("cp.async.commit_group;" ::: "memory")
#define CP_WAIT(n)  asm volatile("cp.async.wait_group %0;" :: "n"(n) : "memory")

__device__ __forceinline__ void ldsm4(uint32_t* r, uint32_t addr) {
    asm volatile("ldmatrix.sync.aligned.m8n8.x4.shared.b16 {%0,%1,%2,%3}, [%4];"
        : "=r"(r[0]), "=r"(r[1]), "=r"(r[2]), "=r"(r[3]) : "r"(addr));
}
__device__ __forceinline__ void ldsm4t(uint32_t* r, uint32_t addr) {
    asm volatile("ldmatrix.sync.aligned.m8n8.x4.trans.shared.b16 {%0,%1,%2,%3}, [%4];"
        : "=r"(r[0]), "=r"(r[1]), "=r"(r[2]), "=r"(r[3]) : "r"(addr));
}
__device__ __forceinline__ void mma_f16(float* d, const uint32_t* a, const uint32_t* b) {
    asm volatile(
        "mma.sync.aligned.m16n8k16.row.col.f32.f16.f16.f32 "
        "{%0,%1,%2,%3}, {%4,%5,%6,%7}, {%8,%9}, {%0,%1,%2,%3};"
        : "+f"(d[0]), "+f"(d[1]), "+f"(d[2]), "+f"(d[3])
        : "r"(a[0]), "r"(a[1]), "r"(a[2]), "r"(a[3]), "r"(b[0]), "r"(b[1]));
}
__device__ __forceinline__ uint32_t h2bits(float x, float y) {
    __half2 h = __floats2half2_rn(x, y);
    return *reinterpret_cast<uint32_t*>(&h);
}

// ---------------- fp16 GEMM with ldmatrix, cp.async 4-stage (frozen R11) ----------------
#define BKK 32
#define STAGES 4
#define ASTRH 40
#define A_HALFS (128 * ASTRH)
#define STAGE_HALFS (2 * A_HALFS)
#define GEMM_SMEM (STAGES * STAGE_HALFS * 2)

__global__ void __launch_bounds__(128, 2) gemm_mma(
    const __half* __restrict__ A, int lda,
    const __half* __restrict__ W,
    const float* __restrict__ bias,
    const float* __restrict__ Res, int ldr,
    float* __restrict__ Cm, __half* __restrict__ Ch, int ldc, int ccol,
    int M, int N, int K, int rowmap, int act, int ropeN)
{
    extern __shared__ __half smh[];
    const uint32_t smb = smem_u32(smh);

    const int tid  = threadIdx.x;
    const int wid  = tid >> 5, lane = tid & 31;
    const int g    = lane >> 2, tig = lane & 3;
    const int wm   = wid & 1,  wn  = wid >> 1;
    const int m0   = wm * 64,  n0  = wn * 64;
    const int bm   = blockIdx.y * 128, bn = blockIdx.x * 128;
    const int nbase = maprow(bm, rowmap);

    float acc[128];
    #pragma unroll
    for (int i = 0; i < 128; i++) acc[i] = 0.f;

    const int row0 = tid >> 2, c0 = (tid & 3) * 8;
    const __half* aP = A + (size_t)(nbase + row0) * lda + c0;
    const __half* bP = W + (size_t)(bn + row0) * K + c0;
    const uint32_t aD0 = (uint32_t)(row0 * ASTRH + c0) * 2;
    const uint32_t bD0 = aD0 + A_HALFS * 2;
    const size_t aStride = (size_t)32 * lda;
    const size_t bStride = (size_t)32 * K;

    uint32_t aB[4], bB[4];
    #pragma unroll
    for (int mt = 0; mt < 4; mt++)
        aB[mt] = smb + (uint32_t)((m0 + mt * 16 + (lane & 15)) * ASTRH + (lane >> 4) * 8) * 2;
    #pragma unroll
    for (int p = 0; p < 4; p++)
        bB[p] = smb + (uint32_t)(A_HALFS
                 + (n0 + p * 16 + (lane & 7) + ((lane >> 4) & 1) * 8) * ASTRH
                 + ((lane >> 3) & 1) * 8) * 2;

    const int nk = K / BKK;

    #pragma unroll
    for (int s = 0; s < STAGES - 1; s++) {
        uint32_t sb = smb + s * (STAGE_HALFS * 2);
        int k0 = s * BKK;
        #pragma unroll
        for (int t = 0; t < 4; t++) cp_async16(sb + aD0 + t * (32 * ASTRH * 2), aP + t * aStride + k0);
        #pragma unroll
        for (int t = 0; t < 4; t++) cp_async16(sb + bD0 + t * (32 * ASTRH * 2), bP + t * bStride + k0);
        CP_COMMIT();
    }

    for (int i = 0; i < nk; i++) {
        CP_WAIT(STAGES - 2);
        __syncthreads();
        {
            int k0 = (i + STAGES - 1) * BKK;
            if (k0 < K) {
                int st = (i + STAGES - 1) % STAGES;
                uint32_t sb = smb + st * (STAGE_HALFS * 2);
                #pragma unroll
                for (int t = 0; t < 4; t++) cp_async16(sb + aD0 + t * (32 * ASTRH * 2), aP + t * aStride + k0);
                #pragma unroll
                for (int t = 0; t < 4; t++) cp_async16(sb + bD0 + t * (32 * ASTRH * 2), bP + t * bStride + k0);
            }
            CP_COMMIT();
        }
        const uint32_t stOff = (i % STAGES) * (STAGE_HALFS * 2);
        #pragma unroll
        for (int k16 = 0; k16 < 2; k16++) {
            const uint32_t kOff = stOff + k16 * 32;
            uint32_t af[4][4], bf[8][2];
            #pragma unroll
            for (int mt = 0; mt < 4; mt++)
                ldsm4(af[mt], aB[mt] + kOff);
            #pragma unroll
            for (int p = 0; p < 4; p++) {
                uint32_t r[4];
                ldsm4(r, bB[p] + kOff);
                bf[2 * p][0] = r[0]; bf[2 * p][1] = r[1];
                bf[2 * p + 1][0] = r[2]; bf[2 * p + 1][1] = r[3];
            }
            #pragma unroll
            for (int mt = 0; mt < 4; mt++)
                #pragma unroll
                for (int nt = 0; nt < 8; nt++)
                    mma_f16(acc + (mt * 8 + nt) * 4, af[mt], bf[nt]);
        }
    }

    #pragma unroll
    for (int mt = 0; mt < 4; mt++) {
        const int rn0 = nbase + m0 + mt * 16 + g;
        const int rn1 = rn0 + 8;
        const size_t o0 = (size_t)rn0 * ldc + ccol;
        const size_t o1 = (size_t)rn1 * ldc + ccol;
        const size_t q0 = (size_t)rn0 * ldr;
        const size_t q1 = (size_t)rn1 * ldr;
        const int r0 = (rn0 >> 6) & 127;
        const int r1 = (rn1 >> 6) & 127;
        #pragma unroll
        for (int nt = 0; nt < 8; nt++) {
            const int c = n0 + nt * 8 + 2 * tig + bn;
            const float2 bv = *reinterpret_cast<const float2*>(bias + c);
            const float* a = acc + (mt * 8 + nt) * 4;
            float v0 = a[0] + bv.x, v1 = a[1] + bv.y;
            float v2 = a[2] + bv.x, v3 = a[3] + bv.y;
            if (act == 1) {
                v0 = 0.5f * v0 * (1.f + erff(v0 * 0.70710678118654752f));
                v1 = 0.5f * v1 * (1.f + erff(v1 * 0.70710678118654752f));
                v2 = 0.5f * v2 * (1.f + erff(v2 * 0.70710678118654752f));
                v3 = 0.5f * v3 * (1.f + erff(v3 * 0.70710678118654752f));
            }
            if (c < ropeN) {
                int pi = ((ccol + c) & 31) >> 1;
                float inv = __expf(-(float)pi * 0.57564627324851148f);
                float s0, c0s, s1, c1s;
                __sincosf((float)r0 * inv, &s0, &c0s);
                __sincosf((float)r1 * inv, &s1, &c1s);
                float e0 = v0, od0 = v1, e1 = v2, od1 = v3;
                v0 = e0 * c0s - od0 * s0;  v1 = e0 * s0 + od0 * c0s;
                v2 = e1 * c1s - od1 * s1;  v3 = e1 * s1 + od1 * c1s;
            }
            if (Res) {
                const float2 rr0 = *reinterpret_cast<const float2*>(Res + q0 + c);
                const float2 rr1 = *reinterpret_cast<const float2*>(Res + q1 + c);
                v0 += rr0.x; v1 += rr0.y; v2 += rr1.x; v3 += rr1.y;
            }
            if (Cm) {
                *reinterpret_cast<float2*>(Cm + o0 + c) = make_float2(v0, v1);
                *reinterpret_cast<float2*>(Cm + o1 + c) = make_float2(v2, v3);
            }
            if (Ch) {
                *reinterpret_cast<uint32_t*>(Ch + o0 + c) = h2bits(v0, v1);
                *reinterpret_cast<uint32_t*>(Ch + o1 + c) = h2bits(v2, v3);
            }
        }
    }
}

// ---------------- float -> half conversion ----------------
__global__ void f2h_kernel(const float4* __restrict__ in, uint4* __restrict__ out, int n8) {
    int i = blockIdx.x * blockDim.x + threadIdx.x;
    if (i >= n8) return;
    float4 a = in[2 * i], b = in[2 * i + 1];
    uint4 o;
    o.x = h2bits(a.x, a.y);
    o.y = h2bits(a.z, a.w);
    o.z = h2bits(b.x, b.y);
    o.w = h2bits(b.z, b.w);
    out[i] = o;
}

// ---------------- LayerNorm: warp per row, optional half copy ----------------
__global__ void __launch_bounds__(256) ln_kernel(
    const float* __restrict__ in, float* __restrict__ out, __half* __restrict__ hout,
    const float* __restrict__ g, const float* __restrict__ b)
{
    const int row  = blockIdx.x * 8 + (threadIdx.x >> 5);
    const int lane = threadIdx.x & 31;
    const float4* p = reinterpret_cast<const float4*>(in + (size_t)row * EE);
    float4 u = p[lane];
    float4 w = p[32 + lane];
    float s = (u.x + u.y) + (u.z + u.w) + (w.x + w.y) + (w.z + w.w);
    #pragma unroll
    for (int o = 16; o; o >>= 1) s += __shfl_xor_sync(0xffffffffu, s, o);
    const float mean = s * (1.0f / EE);
    u.x -= mean; u.y -= mean; u.z -= mean; u.w -= mean;
    w.x -= mean; w.y -= mean; w.z -= mean; w.w -= mean;
    float v = u.x * u.x + u.y * u.y + u.z * u.z + u.w * u.w
            + w.x * w.x + w.y * w.y + w.z * w.z + w.w * w.w;
    #pragma unroll
    for (int o = 16; o; o >>= 1) v += __shfl_xor_sync(0xffffffffu, v, o);
    const float inv = rsqrtf(v * (1.0f / EE) + 1e-5f);
    const float4 g0 = reinterpret_cast<const float4*>(g)[lane];
    const float4 g1 = reinterpret_cast<const float4*>(g)[32 + lane];
    const float4 b0 = reinterpret_cast<const float4*>(b)[lane];
    const float4 b1 = reinterpret_cast<const float4*>(b)[32 + lane];
    float4 o0, o1;
    o0.x = u.x * inv * g0.x + b0.x; o0.y = u.y * inv * g0.y + b0.y;
    o0.z = u.z * inv * g0.z + b0.z; o0.w = u.w * inv * g0.w + b0.w;
    o1.x = w.x * inv * g1.x + b1.x; o1.y = w.y * inv * g1.y + b1.y;
    o1.z = w.z * inv * g1.z + b1.z; o1.w = w.w * inv * g1.w + b1.w;
    float4* q = reinterpret_cast<float4*>(out + (size_t)row * EE);
    q[lane] = o0;
    q[32 + lane] = o1;
    if (hout) {
        uint2 h0, h1;
        h0.x = h2bits(o0.x, o0.y); h0.y = h2bits(o0.z, o0.w);
        h1.x = h2bits(o1.x, o1.y); h1.y = h2bits(o1.z, o1.w);
        uint2* hq = reinterpret_cast<uint2*>(hout + (size_t)row * EE);
        hq[lane] = h0;
        hq[32 + lane] = h1;
    }
}

// ---------------- tensor-core attention ----------------
// One block per (seq, head). LQ/16 warps; warp w handles q rows [16w, 16w+16).
// QK^T and P*V via m16n8k16 HMMA; softmax fp32 in accumulator fragments.
template<int LQ, int LK, int MODEB>
__global__ void attn_mma(
    const __half* __restrict__ qkv, __half* __restrict__ out,
    const int* __restrict__ mask, int q_r0)
{
    constexpr int NW  = LQ / 16;      // warps
    constexpr int NJ  = LK / 8;       // QK n-tiles
    constexpr int NT2 = LK / 16;      // k16 tiles for PV
    constexpr int THREADS = NW * 32;
    constexpr int STR = 40;           // padded smem stride (halves)

    const int seq = blockIdx.x, head = blockIdx.y;
    int base, pstride;
    if (MODEB) { base = (seq >> 6) * 8192 + (seq & 63); pstride = 64; }
    else       { base = seq * 64;                        pstride = 1;  }

    __shared__ __half Qs[LQ * STR];
    __shared__ __half Ks[LK * STR];
    __shared__ __half Vs[LK * STR];
    __shared__ float Bias[LK];

    const int tid = threadIdx.x, wid = tid >> 5, lane = tid & 31;
    const int qoff = head * 32, koff = 256 + head * 32, voff = 512 + head * 32;

    for (int idx = tid; idx < LQ * 4; idx += THREADS) {
        int r = idx >> 2, c = idx & 3;
        *reinterpret_cast<uint4*>(&Qs[r * STR + c * 8]) =
            *reinterpret_cast<const uint4*>(qkv + (size_t)(base + (q_r0 + r) * pstride) * 768 + qoff + c * 8);
    }
    for (int idx = tid; idx < LK * 4; idx += THREADS) {
        int r = idx >> 2, c = idx & 3;
        size_t rn = (size_t)(base + r * pstride) * 768;
        *reinterpret_cast<uint4*>(&Ks[r * STR + c * 8]) =
            *reinterpret_cast<const uint4*>(qkv + rn + koff + c * 8);
        *reinterpret_cast<uint4*>(&Vs[r * STR + c * 8]) =
            *reinterpret_cast<const uint4*>(qkv + rn + voff + c * 8);
    }
    for (int idx = tid; idx < LK; idx += THREADS) {
        float bv = 0.f;
        if (MODEB) { int b = seq >> 6; if (mask[b * 128 + idx] == 0) bv = -1e9f; }
        Bias[idx] = bv;
    }
    __syncthreads();

    const uint32_t smbQ = smem_u32(Qs), smbK = smem_u32(Ks), smbV = smem_u32(Vs);

    // Q fragments: 2 k16 tiles over hd=32
    uint32_t aQ[2][4];
    {
        uint32_t addr = smbQ + (uint32_t)((wid * 16 + (lane & 15)) * STR + (lane >> 4) * 8) * 2;
        ldsm4(aQ[0], addr);
        ldsm4(aQ[1], addr + 32);
    }

    // QK^T
    float sacc[NJ][4];
    #pragma unroll
    for (int j = 0; j < NJ; j++)
        #pragma unroll
        for (int t = 0; t < 4; t++) sacc[j][t] = 0.f;

    #pragma unroll
    for (int p = 0; p < NJ / 2; p++) {
        uint32_t addr = smbK + (uint32_t)((p * 16 + (lane & 7) + ((lane >> 4) & 1) * 8) * STR
                                          + ((lane >> 3) & 1) * 8) * 2;
        uint32_t r0[4], r1[4];
        ldsm4(r0, addr);
        ldsm4(r1, addr + 32);
        { uint32_t b[2] = {r0[0], r0[1]}; mma_f16(sacc[2 * p],     aQ[0], b); }
        { uint32_t b[2] = {r1[0], r1[1]}; mma_f16(sacc[2 * p],     aQ[1], b); }
        { uint32_t b[2] = {r0[2], r0[3]}; mma_f16(sacc[2 * p + 1], aQ[0], b); }
        { uint32_t b[2] = {r1[2], r1[3]}; mma_f16(sacc[2 * p + 1], aQ[1], b); }
    }

    // softmax (rows: r0 = 16*wid + (lane>>2), r1 = r0+8)
    const float scale = 0.17677669529663689f;
    float mx0 = -3.4e38f, mx1 = -3.4e38f;
    #pragma unroll
    for (int j = 0; j < NJ; j++) {
        int col = j * 8 + 2 * (lane & 3);
        float b0 = Bias[col], b1 = Bias[col + 1];
        sacc[j][0] = fmaf(sacc[j][0], scale, b0);
        sacc[j][1] = fmaf(sacc[j][1], scale, b1);
        sacc[j][2] = fmaf(sacc[j][2], scale, b0);
        sacc[j][3] = fmaf(sacc[j][3], scale, b1);
        mx0 = fmaxf(mx0, fmaxf(sacc[j][0], sacc[j][1]));
        mx1 = fmaxf(mx1, fmaxf(sacc[j][2], sacc[j][3]));
    }
    mx0 = fmaxf(mx0, __shfl_xor_sync(0xffffffffu, mx0, 1));
    mx0 = fmaxf(mx0, __shfl_xor_sync(0xffffffffu, mx0, 2));
    mx1 = fmaxf(mx1, __shfl_xor_sync(0xffffffffu, mx1, 1));
    mx1 = fmaxf(mx1, __shfl_xor_sync(0xffffffffu, mx1, 2));
    float sum0 = 0.f, sum1 = 0.f;
    #pragma unroll
    for (int j = 0; j < NJ; j++) {
        float p0 = __expf(sacc[j][0] - mx0);
        float p1 = __expf(sacc[j][1] - mx0);
        float p2 = __expf(sacc[j][2] - mx1);
        float p3 = __expf(sacc[j][3] - mx1);
        sacc[j][0] = p0; sacc[j][1] = p1; sacc[j][2] = p2; sacc[j][3] = p3;
        sum0 += p0 + p1; sum1 += p2 + p3;
    }
    sum0 += __shfl_xor_sync(0xffffffffu, sum0, 1);
    sum0 += __shfl_xor_sync(0xffffffffu, sum0, 2);
    sum1 += __shfl_xor_sync(0xffffffffu, sum1, 1);
    sum1 += __shfl_xor_sync(0xffffffffu, sum1, 2);
    const float inv0 = 1.f / sum0, inv1 = 1.f / sum1;

    // convert P to A-fragments (layout identity: C frag -> A frag)
    uint32_t aP[NT2][4];
    #pragma unroll
    for (int t = 0; t < NT2; t++) {
        aP[t][0] = h2bits(sacc[2 * t][0],     sacc[2 * t][1]);
        aP[t][1] = h2bits(sacc[2 * t][2],     sacc[2 * t][3]);
        aP[t][2] = h2bits(sacc[2 * t + 1][0], sacc[2 * t + 1][1]);
        aP[t][3] = h2bits(sacc[2 * t + 1][2], sacc[2 * t + 1][3]);
    }

    // P*V: V B-fragments via ldmatrix.trans on row-major [key][hd]
    float oacc[4][4];
    #pragma unroll
    for (int n = 0; n < 4; n++)
        #pragma unroll
        for (int t = 0; t < 4; t++) oacc[n][t] = 0.f;

    #pragma unroll
    for (int t = 0; t < NT2; t++) {
        uint32_t addr = smbV + (uint32_t)((16 * t + (lane & 15)) * STR + (lane >> 4) * 8) * 2;
        uint32_t v0[4], v1[4];
        ldsm4t(v0, addr);        // n cols 0..15  (r0,r1: n0-7 k0-7/k8-15; r2,r3: n8-15)
        ldsm4t(v1, addr + 32);   // n cols 16..31
        { uint32_t b[2] = {v0[0], v0[1]}; mma_f16(oacc[0], aP[t], b); }
        { uint32_t b[2] = {v0[2], v0[3]}; mma_f16(oacc[1], aP[t], b); }
        { uint32_t b[2] = {v1[0], v1[1]}; mma_f16(oacc[2], aP[t], b); }
        { uint32_t b[2] = {v1[2], v1[3]}; mma_f16(oacc[3], aP[t], b); }
    }

    // write out: rows 16*wid + (lane>>2) and +8; cols nc*8 + 2*(lane&3)
    const int r0 = 16 * wid + (lane >> 2);
    const int r1 = r0 + 8;
    const size_t o0 = (size_t)(base + (q_r0 + r0) * pstride) * 256 + head * 32;
    const size_t o1 = (size_t)(base + (q_r0 + r1) * pstride) * 256 + head * 32;
    #pragma unroll
    for (int nc = 0; nc < 4; nc++) {
        const int col = nc * 8 + 2 * (lane & 3);
        *reinterpret_cast<uint32_t*>(out + o0 + col) = h2bits(oacc[nc][0] * inv0, oacc[nc][1] * inv0);
        *reinterpret_cast<uint32_t*>(out + o1 + col) = h2bits(oacc[nc][2] * inv1, oacc[nc][3] * inv1);
    }
}

// ---------------- launcher ----------------
extern "C" void kernel_launch(void* const* d_in, const int* in_sizes, int n_in,
                              void* d_out, int out_size) {
    const float* src  = (const float*)d_in[0];
    const int*   mask = (const int*)  d_in[1];
    int wi = 2;
    if (n_in > 2 && in_sizes[2] == 1) wi = 3;
    const float* y_in_w  = (const float*)d_in[wi + 0];
    const float* y_in_b  = (const float*)d_in[wi + 1];
    const float* y_out_w = (const float*)d_in[wi + 2];
    const float* y_out_b = (const float*)d_in[wi + 3];
    const float* x_in_w  = (const float*)d_in[wi + 4];
    const float* x_in_b  = (const float*)d_in[wi + 5];
    const float* x_out_w = (const float*)d_in[wi + 6];
    const float* x_out_b = (const float*)d_in[wi + 7];
    const float* w1      = (const float*)d_in[wi + 8];
    const float* b1      = (const float*)d_in[wi + 9];
    const float* w2      = (const float*)d_in[wi + 10];
    const float* b2      = (const float*)d_in[wi + 11];
    const float* n1_g    = (const float*)d_in[wi + 12];
    const float* n1_b    = (const float*)d_in[wi + 13];
    const float* n2_g    = (const float*)d_in[wi + 14];
    const float* n2_b    = (const float*)d_in[wi + 15];
    const float* n3_g    = (const float*)d_in[wi + 16];
    const float* n3_b    = (const float*)d_in[wi + 17];

    float *Xn, *X2, *X2n;
    __half *QKVh, *ATTh, *Xnh, *X2h, *X2nh, *Hmh, *srch, *Wh;
    cudaGetSymbolAddress((void**)&Xn,   g_Xn);
    cudaGetSymbolAddress((void**)&X2,   g_X2);
    cudaGetSymbolAddress((void**)&X2n,  g_X2n);
    cudaGetSymbolAddress((void**)&QKVh, g_QKVh);
    cudaGetSymbolAddress((void**)&ATTh, g_ATTh);
    cudaGetSymbolAddress((void**)&Xnh,  g_Xnh);
    cudaGetSymbolAddress((void**)&X2h,  g_X2h);
    cudaGetSymbolAddress((void**)&X2nh, g_X2nh);
    cudaGetSymbolAddress((void**)&Hmh,  g_Hmh);
    cudaGetSymbolAddress((void**)&srch, g_srch);
    cudaGetSymbolAddress((void**)&Wh,   g_Wh);

    cudaFuncSetAttribute(gemm_mma, cudaFuncAttributeMaxDynamicSharedMemorySize, GEMM_SMEM);

    // ---- conversions ----
    f2h_kernel<<<(NT * EE / 8 + 255) / 256, 256>>>((const float4*)src, (uint4*)srch, NT * EE / 8);
    f2h_kernel<<<(196608 / 8 + 255) / 256, 256>>>((const float4*)y_in_w,  (uint4*)(Wh + WOFF_YIN),  196608 / 8);
    f2h_kernel<<<(65536  / 8 + 255) / 256, 256>>>((const float4*)y_out_w, (uint4*)(Wh + WOFF_YOUT), 65536 / 8);
    f2h_kernel<<<(196608 / 8 + 255) / 256, 256>>>((const float4*)x_in_w,  (uint4*)(Wh + WOFF_XIN),  196608 / 8);
    f2h_kernel<<<(65536  / 8 + 255) / 256, 256>>>((const float4*)x_out_w, (uint4*)(Wh + WOFF_XOUT), 65536 / 8);
    f2h_kernel<<<(262144 / 8 + 255) / 256, 256>>>((const float4*)w1,      (uint4*)(Wh + WOFF_W1),   262144 / 8);
    f2h_kernel<<<(262144 / 8 + 255) / 256, 256>>>((const float4*)w2,      (uint4*)(Wh + WOFF_W2),   262144 / 8);

    // ---- stage A ----
    gemm_mma<<<dim3(6, 512), 128, GEMM_SMEM>>>(srch, 256, Wh + WOFF_YIN, y_in_b, nullptr, 0,
                                               nullptr, QKVh, 768, 0, NT, 768, 256, 0, 0, 0);
    attn_mma<64, 64, 0><<<dim3(1024, HH), 128>>>(QKVh, ATTh, nullptr, 0);
    gemm_mma<<<dim3(2, 512), 128, GEMM_SMEM>>>(ATTh, 256, Wh + WOFF_YOUT, y_out_b, src, 256,
                                               X2, nullptr, 256, 0, NT, 256, 256, 0, 0, 0);
    ln_kernel<<<NT / 8, 256>>>(X2, Xn, Xnh, n1_g, n1_b);

    // ---- stage B ----
    gemm_mma<<<dim3(6, 384), 128, GEMM_SMEM>>>(Xnh, 256, Wh + WOFF_XIN, x_in_b, nullptr, 0,
                                               nullptr, QKVh, 768, 0, 49152, 768, 256, 1, 0, 512);
    gemm_mma<<<dim3(2, 128), 128, GEMM_SMEM>>>(Xnh, 256, Wh + WOFF_XIN, x_in_b, nullptr, 0,
                                               nullptr, QKVh, 768, 0, 16384, 256, 256, 2, 0, 256);
    attn_mma<96, 96, 1><<<dim3(512, HH), 192>>>(QKVh, ATTh, mask, 0);
    gemm_mma<<<dim3(2, 384), 128, GEMM_SMEM>>>(ATTh, 256, Wh + WOFF_XOUT, x_out_b, Xn, 256,
                                               X2, X2h, 256, 0, 49152, 256, 256, 1, 0, 0);
    gemm_mma<<<dim3(4, 384), 128, GEMM_SMEM>>>(X2h, 256, Wh + WOFF_XIN + 65536, x_in_b + 256,
                                               nullptr, 0, nullptr, QKVh, 768, 256,
                                               49152, 512, 256, 1, 0, 256);
    attn_mma<32, 96, 1><<<dim3(512, HH), 64>>>(QKVh, ATTh, mask, 96);
    gemm_mma<<<dim3(2, 128), 128, GEMM_SMEM>>>(ATTh, 256, Wh + WOFF_XOUT, x_out_b, Xn, 256,
                                               X2, nullptr, 256, 0, 16384, 256, 256, 2, 0, 0);
    ln_kernel<<<NT / 8, 256>>>(X2, X2n, X2nh, n2_g, n2_b);

    // ---- MLP + final LN ----
    gemm_mma<<<dim3(8, 512), 128, GEMM_SMEM>>>(X2nh, 256, Wh + WOFF_W1, b1, nullptr, 0,
                                               nullptr, Hmh, 1024, 0, NT, 1024, 256, 0, 1, 0);
    gemm_mma<<<dim3(2, 512), 128, GEMM_SMEM>>>(Hmh, 1024, Wh + WOFF_W2, b2, X2n, 256,
                                               X2, nullptr, 256, 0, NT, 256, 1024, 0, 0, 0);
    ln_kernel<<<NT / 8, 256>>>(X2, (float*)d_out, nullptr, n3_g, n3_b);
}

// round 14
// speedup vs baseline: 2.0178x; 1.0828x over previous
#include <cuda_runtime.h>
#include <cuda_fp16.h>
#include <math.h>
#include <cstdint>

// ---------------- problem constants ----------------
#define BSZ 8
#define RR  128
#define CC  64
#define EE  256
#define HH  8
#define HD  32
#define SPL 96
#define NT  65536
#define MHID 1024

// ---------------- scratch ----------------
__device__ float  g_X2 [(size_t)NT * EE];
__device__ __half g_QKVh[(size_t)NT * 768];
__device__ __half g_ATTh[(size_t)NT * EE];
__device__ __half g_Xnh [(size_t)NT * EE];
__device__ __half g_X2h [(size_t)NT * EE];
__device__ __half g_X2nh[(size_t)NT * EE];
__device__ __half g_Hmh [(size_t)NT * MHID];
__device__ __half g_srch[(size_t)NT * EE];
__device__ __half g_Wh  [1048576];

#define WOFF_YIN  0
#define WOFF_YOUT 196608
#define WOFF_XIN  262144
#define WOFF_XOUT 458752
#define WOFF_W1   524288
#define WOFF_W2   786432

// mode 0: identity; mode 1: ctx rows (r<96); mode 2: qry rows (r>=96)
__device__ __forceinline__ int maprow(int m, int mode) {
    if (mode == 1) { int b = m / 6144; return b * 8192 + (m - b * 6144); }
    if (mode == 2) { int b = m >> 11;  return b * 8192 + 6144 + (m & 2047); }
    return m;
}

__device__ __forceinline__ uint32_t smem_u32(const void* p) {
    uint32_t a;
    asm("{ .reg .u64 t; cvta.to.shared.u64 t, %1; cvt.u32.u64 %0, t; }" : "=r"(a) : "l"(p));
    return a;
}
__device__ __forceinline__ void cp_async16(uint32_t dst, const void* src) {
    asm volatile("cp.async.cg.shared.global [%0], [%1], 16;" :: "r"(dst), "l"(src));
}
#define CP_COMMIT() asm volatile("cp.async.commit_group;" ::: "memory")
#define CP_WAIT(n)  asm volatile("cp.async.wait_group %0;" :: "n"(n) : "memory")

__device__ __forceinline__ void ldsm4(uint32_t* r, uint32_t addr) {
    asm volatile("ldmatrix.sync.aligned.m8n8.x4.shared.b16 {%0,%1,%2,%3}, [%4];"
        : "=r"(r[0]), "=r"(r[1]), "=r"(r[2]), "=r"(r[3]) : "r"(addr));
}
__device__ __forceinline__ void ldsm4t(uint32_t* r, uint32_t addr) {
    asm volatile("ldmatrix.sync.aligned.m8n8.x4.trans.shared.b16 {%0,%1,%2,%3}, [%4];"
        : "=r"(r[0]), "=r"(r[1]), "=r"(r[2]), "=r"(r[3]) : "r"(addr));
}
__device__ __forceinline__ void mma_f16(float* d, const uint32_t* a, const uint32_t* b) {
    asm volatile(
        "mma.sync.aligned.m16n8k16.row.col.f32.f16.f16.f32 "
        "{%0,%1,%2,%3}, {%4,%5,%6,%7}, {%8,%9}, {%0,%1,%2,%3};"
        : "+f"(d[0]), "+f"(d[1]), "+f"(d[2]), "+f"(d[3])
        : "r"(a[0]), "r"(a[1]), "r"(a[2]), "r"(a[3]), "r"(b[0]), "r"(b[1]));
}
__device__ __forceinline__ uint32_t h2bits(float x, float y) {
    __half2 h = __floats2half2_rn(x, y);
    return *reinterpret_cast<uint32_t*>(&h);
}
__device__ __forceinline__ float fast_gelu(float x) {
    float u = 0.7978845608028654f * fmaf(0.044715f * x, x * x, x);
    float t;
    asm("tanh.approx.f32 %0, %1;" : "=f"(t) : "f"(u));
    return 0.5f * x * (1.f + t);
}

// ---------------- fp16 GEMM with ldmatrix, cp.async 4-stage ----------------
#define BKK 32
#define STAGES 4
#define ASTRH 40
#define A_HALFS (128 * ASTRH)
#define STAGE_HALFS (2 * A_HALFS)
#define GEMM_SMEM (STAGES * STAGE_HALFS * 2)

__global__ void __launch_bounds__(128, 2) gemm_mma(
    const __half* __restrict__ A, int lda,
    const __half* __restrict__ W,
    const float* __restrict__ bias,
    const __half* __restrict__ Res, int ldr,       // residual now half
    float* __restrict__ Cm, __half* __restrict__ Ch, int ldc, int ccol,
    int M, int N, int K, int rowmap, int act, int ropeN)
{
    extern __shared__ __half smh[];
    const uint32_t smb = smem_u32(smh);

    const int tid  = threadIdx.x;
    const int wid  = tid >> 5, lane = tid & 31;
    const int g    = lane >> 2, tig = lane & 3;
    const int wm   = wid & 1,  wn  = wid >> 1;
    const int m0   = wm * 64,  n0  = wn * 64;
    const int bm   = blockIdx.y * 128, bn = blockIdx.x * 128;
    const int nbase = maprow(bm, rowmap);

    float acc[128];
    #pragma unroll
    for (int i = 0; i < 128; i++) acc[i] = 0.f;

    const int row0 = tid >> 2, c0 = (tid & 3) * 8;
    const __half* aP = A + (size_t)(nbase + row0) * lda + c0;
    const __half* bP = W + (size_t)(bn + row0) * K + c0;
    const uint32_t aD0 = (uint32_t)(row0 * ASTRH + c0) * 2;
    const uint32_t bD0 = aD0 + A_HALFS * 2;
    const size_t aStride = (size_t)32 * lda;
    const size_t bStride = (size_t)32 * K;

    uint32_t aB[4], bB[4];
    #pragma unroll
    for (int mt = 0; mt < 4; mt++)
        aB[mt] = smb + (uint32_t)((m0 + mt * 16 + (lane & 15)) * ASTRH + (lane >> 4) * 8) * 2;
    #pragma unroll
    for (int p = 0; p < 4; p++)
        bB[p] = smb + (uint32_t)(A_HALFS
                 + (n0 + p * 16 + (lane & 7) + ((lane >> 4) & 1) * 8) * ASTRH
                 + ((lane >> 3) & 1) * 8) * 2;

    const int nk = K / BKK;

    #pragma unroll
    for (int s = 0; s < STAGES - 1; s++) {
        uint32_t sb = smb + s * (STAGE_HALFS * 2);
        int k0 = s * BKK;
        #pragma unroll
        for (int t = 0; t < 4; t++) cp_async16(sb + aD0 + t * (32 * ASTRH * 2), aP + t * aStride + k0);
        #pragma unroll
        for (int t = 0; t < 4; t++) cp_async16(sb + bD0 + t * (32 * ASTRH * 2), bP + t * bStride + k0);
        CP_COMMIT();
    }

    for (int i = 0; i < nk; i++) {
        CP_WAIT(STAGES - 2);
        __syncthreads();
        {
            int k0 = (i + STAGES - 1) * BKK;
            if (k0 < K) {
                int st = (i + STAGES - 1) % STAGES;
                uint32_t sb = smb + st * (STAGE_HALFS * 2);
                #pragma unroll
                for (int t = 0; t < 4; t++) cp_async16(sb + aD0 + t * (32 * ASTRH * 2), aP + t * aStride + k0);
                #pragma unroll
                for (int t = 0; t < 4; t++) cp_async16(sb + bD0 + t * (32 * ASTRH * 2), bP + t * bStride + k0);
            }
            CP_COMMIT();
        }
        const uint32_t stOff = (i % STAGES) * (STAGE_HALFS * 2);
        #pragma unroll
        for (int k16 = 0; k16 < 2; k16++) {
            const uint32_t kOff = stOff + k16 * 32;
            uint32_t af[4][4], bf[8][2];
            #pragma unroll
            for (int mt = 0; mt < 4; mt++)
                ldsm4(af[mt], aB[mt] + kOff);
            #pragma unroll
            for (int p = 0; p < 4; p++) {
                uint32_t r[4];
                ldsm4(r, bB[p] + kOff);
                bf[2 * p][0] = r[0]; bf[2 * p][1] = r[1];
                bf[2 * p + 1][0] = r[2]; bf[2 * p + 1][1] = r[3];
            }
            #pragma unroll
            for (int mt = 0; mt < 4; mt++)
                #pragma unroll
                for (int nt = 0; nt < 8; nt++)
                    mma_f16(acc + (mt * 8 + nt) * 4, af[mt], bf[nt]);
        }
    }

    #pragma unroll
    for (int mt = 0; mt < 4; mt++) {
        const int rn0 = nbase + m0 + mt * 16 + g;
        const int rn1 = rn0 + 8;
        const size_t o0 = (size_t)rn0 * ldc + ccol;
        const size_t o1 = (size_t)rn1 * ldc + ccol;
        const size_t q0 = (size_t)rn0 * ldr;
        const size_t q1 = (size_t)rn1 * ldr;
        const int r0 = (rn0 >> 6) & 127;
        const int r1 = (rn1 >> 6) & 127;
        #pragma unroll
        for (int nt = 0; nt < 8; nt++) {
            const int c = n0 + nt * 8 + 2 * tig + bn;
            const float2 bv = *reinterpret_cast<const float2*>(bias + c);
            const float* a = acc + (mt * 8 + nt) * 4;
            float v0 = a[0] + bv.x, v1 = a[1] + bv.y;
            float v2 = a[2] + bv.x, v3 = a[3] + bv.y;
            if (act == 1) {
                v0 = fast_gelu(v0);
                v1 = fast_gelu(v1);
                v2 = fast_gelu(v2);
                v3 = fast_gelu(v3);
            }
            if (c < ropeN) {
                int pi = ((ccol + c) & 31) >> 1;
                float inv = __expf(-(float)pi * 0.57564627324851148f);
                float s0, c0s, s1, c1s;
                __sincosf((float)r0 * inv, &s0, &c0s);
                __sincosf((float)r1 * inv, &s1, &c1s);
                float e0 = v0, od0 = v1, e1 = v2, od1 = v3;
                v0 = e0 * c0s - od0 * s0;  v1 = e0 * s0 + od0 * c0s;
                v2 = e1 * c1s - od1 * s1;  v3 = e1 * s1 + od1 * c1s;
            }
            if (Res) {
                float2 rr0 = __half22float2(*reinterpret_cast<const __half2*>(Res + q0 + c));
                float2 rr1 = __half22float2(*reinterpret_cast<const __half2*>(Res + q1 + c));
                v0 += rr0.x; v1 += rr0.y; v2 += rr1.x; v3 += rr1.y;
            }
            if (Cm) {
                *reinterpret_cast<float2*>(Cm + o0 + c) = make_float2(v0, v1);
                *reinterpret_cast<float2*>(Cm + o1 + c) = make_float2(v2, v3);
            }
            if (Ch) {
                *reinterpret_cast<uint32_t*>(Ch + o0 + c) = h2bits(v0, v1);
                *reinterpret_cast<uint32_t*>(Ch + o1 + c) = h2bits(v2, v3);
            }
        }
    }
}

// ---------------- float -> half conversion ----------------
__global__ void f2h_kernel(const float4* __restrict__ in, uint4* __restrict__ out, int n8) {
    int i = blockIdx.x * blockDim.x + threadIdx.x;
    if (i >= n8) return;
    float4 a = in[2 * i], b = in[2 * i + 1];
    uint4 o;
    o.x = h2bits(a.x, a.y);
    o.y = h2bits(a.z, a.w);
    o.z = h2bits(b.x, b.y);
    o.w = h2bits(b.z, b.w);
    out[i] = o;
}

// all 6 weight tensors in one launch (segment boundaries == WOFF/8)
__global__ void f2h_weights(const float4* yinw, const float4* youtw, const float4* xinw,
                            const float4* xoutw, const float4* w1, const float4* w2,
                            uint4* dst) {
    int i = blockIdx.x * blockDim.x + threadIdx.x;   // uint4-group index, 131072 total
    const float4* src; int l;
    if      (i < 24576)  { src = yinw;  l = i; }
    else if (i < 32768)  { src = youtw; l = i - 24576; }
    else if (i < 57344)  { src = xinw;  l = i - 32768; }
    else if (i < 65536)  { src = xoutw; l = i - 57344; }
    else if (i < 98304)  { src = w1;    l = i - 65536; }
    else                 { src = w2;    l = i - 98304; }
    float4 a = src[2 * l], b = src[2 * l + 1];
    uint4 o;
    o.x = h2bits(a.x, a.y);
    o.y = h2bits(a.z, a.w);
    o.z = h2bits(b.x, b.y);
    o.w = h2bits(b.z, b.w);
    dst[i] = o;
}

// ---------------- LayerNorm: warp per row; fp32 out and/or half out optional ----------------
__global__ void __launch_bounds__(256) ln_kernel(
    const float* __restrict__ in, float* __restrict__ out, __half* __restrict__ hout,
    const float* __restrict__ g, const float* __restrict__ b)
{
    const int row  = blockIdx.x * 8 + (threadIdx.x >> 5);
    const int lane = threadIdx.x & 31;
    const float4* p = reinterpret_cast<const float4*>(in + (size_t)row * EE);
    float4 u = p[lane];
    float4 w = p[32 + lane];
    float s = (u.x + u.y) + (u.z + u.w) + (w.x + w.y) + (w.z + w.w);
    #pragma unroll
    for (int o = 16; o; o >>= 1) s += __shfl_xor_sync(0xffffffffu, s, o);
    const float mean = s * (1.0f / EE);
    u.x -= mean; u.y -= mean; u.z -= mean; u.w -= mean;
    w.x -= mean; w.y -= mean; w.z -= mean; w.w -= mean;
    float v = u.x * u.x + u.y * u.y + u.z * u.z + u.w * u.w
            + w.x * w.x + w.y * w.y + w.z * w.z + w.w * w.w;
    #pragma unroll
    for (int o = 16; o; o >>= 1) v += __shfl_xor_sync(0xffffffffu, v, o);
    const float inv = rsqrtf(v * (1.0f / EE) + 1e-5f);
    const float4 g0 = reinterpret_cast<const float4*>(g)[lane];
    const float4 g1 = reinterpret_cast<const float4*>(g)[32 + lane];
    const float4 b0 = reinterpret_cast<const float4*>(b)[lane];
    const float4 b1 = reinterpret_cast<const float4*>(b)[32 + lane];
    float4 o0, o1;
    o0.x = u.x * inv * g0.x + b0.x; o0.y = u.y * inv * g0.y + b0.y;
    o0.z = u.z * inv * g0.z + b0.z; o0.w = u.w * inv * g0.w + b0.w;
    o1.x = w.x * inv * g1.x + b1.x; o1.y = w.y * inv * g1.y + b1.y;
    o1.z = w.z * inv * g1.z + b1.z; o1.w = w.w * inv * g1.w + b1.w;
    if (out) {
        float4* q = reinterpret_cast<float4*>(out + (size_t)row * EE);
        q[lane] = o0;
        q[32 + lane] = o1;
    }
    if (hout) {
        uint2 h0, h1;
        h0.x = h2bits(o0.x, o0.y); h0.y = h2bits(o0.z, o0.w);
        h1.x = h2bits(o1.x, o1.y); h1.y = h2bits(o1.z, o1.w);
        uint2* hq = reinterpret_cast<uint2*>(hout + (size_t)row * EE);
        hq[lane] = h0;
        hq[32 + lane] = h1;
    }
}

// ---------------- tensor-core attention (frozen R13) ----------------
template<int LQ, int LK, int MODEB>
__global__ void attn_mma(
    const __half* __restrict__ qkv, __half* __restrict__ out,
    const int* __restrict__ mask, int q_r0)
{
    constexpr int NW  = LQ / 16;
    constexpr int NJ  = LK / 8;
    constexpr int NT2 = LK / 16;
    constexpr int THREADS = NW * 32;
    constexpr int STR = 40;

    const int seq = blockIdx.x, head = blockIdx.y;
    int base, pstride;
    if (MODEB) { base = (seq >> 6) * 8192 + (seq & 63); pstride = 64; }
    else       { base = seq * 64;                        pstride = 1;  }

    __shared__ __half Qs[LQ * STR];
    __shared__ __half Ks[LK * STR];
    __shared__ __half Vs[LK * STR];
    __shared__ float Bias[LK];

    const int tid = threadIdx.x, wid = tid >> 5, lane = tid & 31;
    const int qoff = head * 32, koff = 256 + head * 32, voff = 512 + head * 32;

    for (int idx = tid; idx < LQ * 4; idx += THREADS) {
        int r = idx >> 2, c = idx & 3;
        *reinterpret_cast<uint4*>(&Qs[r * STR + c * 8]) =
            *reinterpret_cast<const uint4*>(qkv + (size_t)(base + (q_r0 + r) * pstride) * 768 + qoff + c * 8);
    }
    for (int idx = tid; idx < LK * 4; idx += THREADS) {
        int r = idx >> 2, c = idx & 3;
        size_t rn = (size_t)(base + r * pstride) * 768;
        *reinterpret_cast<uint4*>(&Ks[r * STR + c * 8]) =
            *reinterpret_cast<const uint4*>(qkv + rn + koff + c * 8);
        *reinterpret_cast<uint4*>(&Vs[r * STR + c * 8]) =
            *reinterpret_cast<const uint4*>(qkv + rn + voff + c * 8);
    }
    for (int idx = tid; idx < LK; idx += THREADS) {
        float bv = 0.f;
        if (MODEB) { int b = seq >> 6; if (mask[b * 128 + idx] == 0) bv = -1e9f; }
        Bias[idx] = bv;
    }
    __syncthreads();

    const uint32_t smbQ = smem_u32(Qs), smbK = smem_u32(Ks), smbV = smem_u32(Vs);

    uint32_t aQ[2][4];
    {
        uint32_t addr = smbQ + (uint32_t)((wid * 16 + (lane & 15)) * STR + (lane >> 4) * 8) * 2;
        ldsm4(aQ[0], addr);
        ldsm4(aQ[1], addr + 32);
    }

    float sacc[NJ][4];
    #pragma unroll
    for (int j = 0; j < NJ; j++)
        #pragma unroll
        for (int t = 0; t < 4; t++) sacc[j][t] = 0.f;

    #pragma unroll
    for (int p = 0; p < NJ / 2; p++) {
        uint32_t addr = smbK + (uint32_t)((p * 16 + (lane & 7) + ((lane >> 4) & 1) * 8) * STR
                                          + ((lane >> 3) & 1) * 8) * 2;
        uint32_t r0[4], r1[4];
        ldsm4(r0, addr);
        ldsm4(r1, addr + 32);
        { uint32_t b[2] = {r0[0], r0[1]}; mma_f16(sacc[2 * p],     aQ[0], b); }
        { uint32_t b[2] = {r1[0], r1[1]}; mma_f16(sacc[2 * p],     aQ[1], b); }
        { uint32_t b[2] = {r0[2], r0[3]}; mma_f16(sacc[2 * p + 1], aQ[0], b); }
        { uint32_t b[2] = {r1[2], r1[3]}; mma_f16(sacc[2 * p + 1], aQ[1], b); }
    }

    const float scale = 0.17677669529663689f;
    float mx0 = -3.4e38f, mx1 = -3.4e38f;
    #pragma unroll
    for (int j = 0; j < NJ; j++) {
        int col = j * 8 + 2 * (lane & 3);
        float b0 = Bias[col], b1 = Bias[col + 1];
        sacc[j][0] = fmaf(sacc[j][0], scale, b0);
        sacc[j][1] = fmaf(sacc[j][1], scale, b1);
        sacc[j][2] = fmaf(sacc[j][2], scale, b0);
        sacc[j][3] = fmaf(sacc[j][3], scale, b1);
        mx0 = fmaxf(mx0, fmaxf(sacc[j][0], sacc[j][1]));
        mx1 = fmaxf(mx1, fmaxf(sacc[j][2], sacc[j][3]));
    }
    mx0 = fmaxf(mx0, __shfl_xor_sync(0xffffffffu, mx0, 1));
    mx0 = fmaxf(mx0, __shfl_xor_sync(0xffffffffu, mx0, 2));
    mx1 = fmaxf(mx1, __shfl_xor_sync(0xffffffffu, mx1, 1));
    mx1 = fmaxf(mx1, __shfl_xor_sync(0xffffffffu, mx1, 2));
    float sum0 = 0.f, sum1 = 0.f;
    #pragma unroll
    for (int j = 0; j < NJ; j++) {
        float p0 = __expf(sacc[j][0] - mx0);
        float p1 = __expf(sacc[j][1] - mx0);
        float p2 = __expf(sacc[j][2] - mx1);
        float p3 = __expf(sacc[j][3] - mx1);
        sacc[j][0] = p0; sacc[j][1] = p1; sacc[j][2] = p2; sacc[j][3] = p3;
        sum0 += p0 + p1; sum1 += p2 + p3;
    }
    sum0 += __shfl_xor_sync(0xffffffffu, sum0, 1);
    sum0 += __shfl_xor_sync(0xffffffffu, sum0, 2);
    sum1 += __shfl_xor_sync(0xffffffffu, sum1, 1);
    sum1 += __shfl_xor_sync(0xffffffffu, sum1, 2);
    const float inv0 = 1.f / sum0, inv1 = 1.f / sum1;

    uint32_t aP[NT2][4];
    #pragma unroll
    for (int t = 0; t < NT2; t++) {
        aP[t][0] = h2bits(sacc[2 * t][0],     sacc[2 * t][1]);
        aP[t][1] = h2bits(sacc[2 * t][2],     sacc[2 * t][3]);
        aP[t][2] = h2bits(sacc[2 * t + 1][0], sacc[2 * t + 1][1]);
        aP[t][3] = h2bits(sacc[2 * t + 1][2], sacc[2 * t + 1][3]);
    }

    float oacc[4][4];
    #pragma unroll
    for (int n = 0; n < 4; n++)
        #pragma unroll
        for (int t = 0; t < 4; t++) oacc[n][t] = 0.f;

    #pragma unroll
    for (int t = 0; t < NT2; t++) {
        uint32_t addr = smbV + (uint32_t)((16 * t + (lane & 15)) * STR + (lane >> 4) * 8) * 2;
        uint32_t v0[4], v1[4];
        ldsm4t(v0, addr);
        ldsm4t(v1, addr + 32);
        { uint32_t b[2] = {v0[0], v0[1]}; mma_f16(oacc[0], aP[t], b); }
        { uint32_t b[2] = {v0[2], v0[3]}; mma_f16(oacc[1], aP[t], b); }
        { uint32_t b[2] = {v1[0], v1[1]}; mma_f16(oacc[2], aP[t], b); }
        { uint32_t b[2] = {v1[2], v1[3]}; mma_f16(oacc[3], aP[t], b); }
    }

    const int r0 = 16 * wid + (lane >> 2);
    const int r1 = r0 + 8;
    const size_t o0 = (size_t)(base + (q_r0 + r0) * pstride) * 256 + head * 32;
    const size_t o1 = (size_t)(base + (q_r0 + r1) * pstride) * 256 + head * 32;
    #pragma unroll
    for (int nc = 0; nc < 4; nc++) {
        const int col = nc * 8 + 2 * (lane & 3);
        *reinterpret_cast<uint32_t*>(out + o0 + col) = h2bits(oacc[nc][0] * inv0, oacc[nc][1] * inv0);
        *reinterpret_cast<uint32_t*>(out + o1 + col) = h2bits(oacc[nc][2] * inv1, oacc[nc][3] * inv1);
    }
}

// ---------------- launcher ----------------
extern "C" void kernel_launch(void* const* d_in, const int* in_sizes, int n_in,
                              void* d_out, int out_size) {
    const float* src  = (const float*)d_in[0];
    const int*   mask = (const int*)  d_in[1];
    int wi = 2;
    if (n_in > 2 && in_sizes[2] == 1) wi = 3;
    const float* y_in_w  = (const float*)d_in[wi + 0];
    const float* y_in_b  = (const float*)d_in[wi + 1];
    const float* y_out_w = (const float*)d_in[wi + 2];
    const float* y_out_b = (const float*)d_in[wi + 3];
    const float* x_in_w  = (const float*)d_in[wi + 4];
    const float* x_in_b  = (const float*)d_in[wi + 5];
    const float* x_out_w = (const float*)d_in[wi + 6];
    const float* x_out_b = (const float*)d_in[wi + 7];
    const float* w1      = (const float*)d_in[wi + 8];
    const float* b1      = (const float*)d_in[wi + 9];
    const float* w2      = (const float*)d_in[wi + 10];
    const float* b2      = (const float*)d_in[wi + 11];
    const float* n1_g    = (const float*)d_in[wi + 12];
    const float* n1_b    = (const float*)d_in[wi + 13];
    const float* n2_g    = (const float*)d_in[wi + 14];
    const float* n2_b    = (const float*)d_in[wi + 15];
    const float* n3_g    = (const float*)d_in[wi + 16];
    const float* n3_b    = (const float*)d_in[wi + 17];

    float *X2;
    __half *QKVh, *ATTh, *Xnh, *X2h, *X2nh, *Hmh, *srch, *Wh;
    cudaGetSymbolAddress((void**)&X2,   g_X2);
    cudaGetSymbolAddress((void**)&QKVh, g_QKVh);
    cudaGetSymbolAddress((void**)&ATTh, g_ATTh);
    cudaGetSymbolAddress((void**)&Xnh,  g_Xnh);
    cudaGetSymbolAddress((void**)&X2h,  g_X2h);
    cudaGetSymbolAddress((void**)&X2nh, g_X2nh);
    cudaGetSymbolAddress((void**)&Hmh,  g_Hmh);
    cudaGetSymbolAddress((void**)&srch, g_srch);
    cudaGetSymbolAddress((void**)&Wh,   g_Wh);

    cudaFuncSetAttribute(gemm_mma, cudaFuncAttributeMaxDynamicSharedMemorySize, GEMM_SMEM);

    // ---- conversions ----
    f2h_kernel<<<(NT * EE / 8 + 255) / 256, 256>>>((const float4*)src, (uint4*)srch, NT * EE / 8);
    f2h_weights<<<512, 256>>>((const float4*)y_in_w, (const float4*)y_out_w,
                              (const float4*)x_in_w, (const float4*)x_out_w,
                              (const float4*)w1, (const float4*)w2, (uint4*)Wh);

    // ---- stage A ----
    gemm_mma<<<dim3(6, 512), 128, GEMM_SMEM>>>(srch, 256, Wh + WOFF_YIN, y_in_b, nullptr, 0,
                                               nullptr, QKVh, 768, 0, NT, 768, 256, 0, 0, 0);
    attn_mma<64, 64, 0><<<dim3(1024, HH), 128>>>(QKVh, ATTh, nullptr, 0);
    gemm_mma<<<dim3(2, 512), 128, GEMM_SMEM>>>(ATTh, 256, Wh + WOFF_YOUT, y_out_b, srch, 256,
                                               X2, nullptr, 256, 0, NT, 256, 256, 0, 0, 0);
    ln_kernel<<<NT / 8, 256>>>(X2, nullptr, Xnh, n1_g, n1_b);

    // ---- stage B ----
    gemm_mma<<<dim3(6, 384), 128, GEMM_SMEM>>>(Xnh, 256, Wh + WOFF_XIN, x_in_b, nullptr, 0,
                                               nullptr, QKVh, 768, 0, 49152, 768, 256, 1, 0, 512);
    gemm_mma<<<dim3(2, 128), 128, GEMM_SMEM>>>(Xnh, 256, Wh + WOFF_XIN, x_in_b, nullptr, 0,
                                               nullptr, QKVh, 768, 0, 16384, 256, 256, 2, 0, 256);
    attn_mma<96, 96, 1><<<dim3(512, HH), 192>>>(QKVh, ATTh, mask, 0);
    gemm_mma<<<dim3(2, 384), 128, GEMM_SMEM>>>(ATTh, 256, Wh + WOFF_XOUT, x_out_b, Xnh, 256,
                                               X2, X2h, 256, 0, 49152, 256, 256, 1, 0, 0);
    gemm_mma<<<dim3(4, 384), 128, GEMM_SMEM>>>(X2h, 256, Wh + WOFF_XIN + 65536, x_in_b + 256,
                                               nullptr, 0, nullptr, QKVh, 768, 256,
                                               49152, 512, 256, 1, 0, 256);
    attn_mma<32, 96, 1><<<dim3(512, HH), 64>>>(QKVh, ATTh, mask, 96);
    gemm_mma<<<dim3(2, 128), 128, GEMM_SMEM>>>(ATTh, 256, Wh + WOFF_XOUT, x_out_b, Xnh, 256,
                                               X2, nullptr, 256, 0, 16384, 256, 256, 2, 0, 0);
    ln_kernel<<<NT / 8, 256>>>(X2, nullptr, X2nh, n2_g, n2_b);

    // ---- MLP + final LN ----
    gemm_mma<<<dim3(8, 512), 128, GEMM_SMEM>>>(X2nh, 256, Wh + WOFF_W1, b1, nullptr, 0,
                                               nullptr, Hmh, 1024, 0, NT, 1024, 256, 0, 1, 0);
    gemm_mma<<<dim3(2, 512), 128, GEMM_SMEM>>>(Hmh, 1024, Wh + WOFF_W2, b2, X2nh, 256,
                                               X2, nullptr, 256, 0, NT, 256, 1024, 0, 0, 0);
    ln_kernel<<<NT / 8, 256>>>(X2, (float*)d_out, nullptr, n3_g, n3_b);
}

// round 17
// speedup vs baseline: 2.0648x; 1.0233x over previous
#include <cuda_runtime.h>
#include <cuda_fp16.h>
#include <math.h>
#include <cstdint>

// ---------------- problem constants ----------------
#define BSZ 8
#define RR  128
#define CC  64
#define EE  256
#define HH  8
#define HD  32
#define SPL 96
#define NT  65536
#define MHID 1024

// ---------------- scratch ----------------
__device__ __half g_QKVh[(size_t)NT * 768];
__device__ __half g_ATTh[(size_t)NT * EE];
__device__ __half g_Xnh [(size_t)NT * EE];
__device__ __half g_X2h [(size_t)NT * EE];
__device__ __half g_X2nh[(size_t)NT * EE];
__device__ __half g_Hmh [(size_t)NT * MHID];
__device__ __half g_srch[(size_t)NT * EE];
__device__ __half g_Wh  [1048576];

#define WOFF_YIN  0
#define WOFF_YOUT 196608
#define WOFF_XIN  262144
#define WOFF_XOUT 458752
#define WOFF_W1   524288
#define WOFF_W2   786432

// mode 0: identity; mode 1: ctx rows (r<96); mode 2: qry rows (r>=96)
__device__ __forceinline__ int maprow(int m, int mode) {
    if (mode == 1) { int b = m / 6144; return b * 8192 + (m - b * 6144); }
    if (mode == 2) { int b = m >> 11;  return b * 8192 + 6144 + (m & 2047); }
    return m;
}

__device__ __forceinline__ uint32_t smem_u32(const void* p) {
    uint32_t a;
    asm("{ .reg .u64 t; cvta.to.shared.u64 t, %1; cvt.u32.u64 %0, t; }" : "=r"(a) : "l"(p));
    return a;
}
__device__ __forceinline__ void cp_async16(uint32_t dst, const void* src) {
    asm volatile("cp.async.cg.shared.global [%0], [%1], 16;" :: "r"(dst), "l"(src));
}
#define CP_COMMIT() asm volatile("cp.async.commit_group;" ::: "memory")
#define CP_WAIT(n)  asm volatile("cp.async.wait_group %0;" :: "n"(n) : "memory")

__device__ __forceinline__ void ldsm4(uint32_t* r, uint32_t addr) {
    asm volatile("ldmatrix.sync.aligned.m8n8.x4.shared.b16 {%0,%1,%2,%3}, [%4];"
        : "=r"(r[0]), "=r"(r[1]), "=r"(r[2]), "=r"(r[3]) : "r"(addr));
}
__device__ __forceinline__ void ldsm4t(uint32_t* r, uint32_t addr) {
    asm volatile("ldmatrix.sync.aligned.m8n8.x4.trans.shared.b16 {%0,%1,%2,%3}, [%4];"
        : "=r"(r[0]), "=r"(r[1]), "=r"(r[2]), "=r"(r[3]) : "r"(addr));
}
__device__ __forceinline__ void mma_f16(float* d, const uint32_t* a, const uint32_t* b) {
    asm volatile(
        "mma.sync.aligned.m16n8k16.row.col.f32.f16.f16.f32 "
        "{%0,%1,%2,%3}, {%4,%5,%6,%7}, {%8,%9}, {%0,%1,%2,%3};"
        : "+f"(d[0]), "+f"(d[1]), "+f"(d[2]), "+f"(d[3])
        : "r"(a[0]), "r"(a[1]), "r"(a[2]), "r"(a[3]), "r"(b[0]), "r"(b[1]));
}
__device__ __forceinline__ uint32_t h2bits(float x, float y) {
    __half2 h = __floats2half2_rn(x, y);
    return *reinterpret_cast<uint32_t*>(&h);
}
__device__ __forceinline__ float fast_gelu(float x) {
    float u = 0.7978845608028654f * fmaf(0.044715f * x, x * x, x);
    float t;
    asm("tanh.approx.f32 %0, %1;" : "=f"(t) : "f"(u));
    return 0.5f * x * (1.f + t);
}

// ---------------- fp16 GEMM with ldmatrix, cp.async 4-stage (frozen R11) ----------------
#define BKK 32
#define STAGES 4
#define ASTRH 40
#define A_HALFS (128 * ASTRH)
#define STAGE_HALFS (2 * A_HALFS)
#define GEMM_SMEM (STAGES * STAGE_HALFS * 2)

__global__ void __launch_bounds__(128, 2) gemm_mma(
    const __half* __restrict__ A, int lda,
    const __half* __restrict__ W,
    const float* __restrict__ bias,
    const __half* __restrict__ Res, int ldr,
    float* __restrict__ Cm, __half* __restrict__ Ch, int ldc, int ccol,
    int M, int N, int K, int rowmap, int act, int ropeN)
{
    extern __shared__ __half smh[];
    const uint32_t smb = smem_u32(smh);

    const int tid  = threadIdx.x;
    const int wid  = tid >> 5, lane = tid & 31;
    const int g    = lane >> 2, tig = lane & 3;
    const int wm   = wid & 1,  wn  = wid >> 1;
    const int m0   = wm * 64,  n0  = wn * 64;
    const int bm   = blockIdx.y * 128, bn = blockIdx.x * 128;
    const int nbase = maprow(bm, rowmap);

    float acc[128];
    #pragma unroll
    for (int i = 0; i < 128; i++) acc[i] = 0.f;

    const int row0 = tid >> 2, c0 = (tid & 3) * 8;
    const __half* aP = A + (size_t)(nbase + row0) * lda + c0;
    const __half* bP = W + (size_t)(bn + row0) * K + c0;
    const uint32_t aD0 = (uint32_t)(row0 * ASTRH + c0) * 2;
    const uint32_t bD0 = aD0 + A_HALFS * 2;
    const size_t aStride = (size_t)32 * lda;
    const size_t bStride = (size_t)32 * K;

    uint32_t aB[4], bB[4];
    #pragma unroll
    for (int mt = 0; mt < 4; mt++)
        aB[mt] = smb + (uint32_t)((m0 + mt * 16 + (lane & 15)) * ASTRH + (lane >> 4) * 8) * 2;
    #pragma unroll
    for (int p = 0; p < 4; p++)
        bB[p] = smb + (uint32_t)(A_HALFS
                 + (n0 + p * 16 + (lane & 7) + ((lane >> 4) & 1) * 8) * ASTRH
                 + ((lane >> 3) & 1) * 8) * 2;

    const int nk = K / BKK;

    #pragma unroll
    for (int s = 0; s < STAGES - 1; s++) {
        uint32_t sb = smb + s * (STAGE_HALFS * 2);
        int k0 = s * BKK;
        #pragma unroll
        for (int t = 0; t < 4; t++) cp_async16(sb + aD0 + t * (32 * ASTRH * 2), aP + t * aStride + k0);
        #pragma unroll
        for (int t = 0; t < 4; t++) cp_async16(sb + bD0 + t * (32 * ASTRH * 2), bP + t * bStride + k0);
        CP_COMMIT();
    }

    for (int i = 0; i < nk; i++) {
        CP_WAIT(STAGES - 2);
        __syncthreads();
        {
            int k0 = (i + STAGES - 1) * BKK;
            if (k0 < K) {
                int st = (i + STAGES - 1) % STAGES;
                uint32_t sb = smb + st * (STAGE_HALFS * 2);
                #pragma unroll
                for (int t = 0; t < 4; t++) cp_async16(sb + aD0 + t * (32 * ASTRH * 2), aP + t * aStride + k0);
                #pragma unroll
                for (int t = 0; t < 4; t++) cp_async16(sb + bD0 + t * (32 * ASTRH * 2), bP + t * bStride + k0);
            }
            CP_COMMIT();
        }
        const uint32_t stOff = (i % STAGES) * (STAGE_HALFS * 2);
        #pragma unroll
        for (int k16 = 0; k16 < 2; k16++) {
            const uint32_t kOff = stOff + k16 * 32;
            uint32_t af[4][4], bf[8][2];
            #pragma unroll
            for (int mt = 0; mt < 4; mt++)
                ldsm4(af[mt], aB[mt] + kOff);
            #pragma unroll
            for (int p = 0; p < 4; p++) {
                uint32_t r[4];
                ldsm4(r, bB[p] + kOff);
                bf[2 * p][0] = r[0]; bf[2 * p][1] = r[1];
                bf[2 * p + 1][0] = r[2]; bf[2 * p + 1][1] = r[3];
            }
            #pragma unroll
            for (int mt = 0; mt < 4; mt++)
                #pragma unroll
                for (int nt = 0; nt < 8; nt++)
                    mma_f16(acc + (mt * 8 + nt) * 4, af[mt], bf[nt]);
        }
    }

    #pragma unroll
    for (int mt = 0; mt < 4; mt++) {
        const int rn0 = nbase + m0 + mt * 16 + g;
        const int rn1 = rn0 + 8;
        const size_t o0 = (size_t)rn0 * ldc + ccol;
        const size_t o1 = (size_t)rn1 * ldc + ccol;
        const size_t q0 = (size_t)rn0 * ldr;
        const size_t q1 = (size_t)rn1 * ldr;
        const int r0 = (rn0 >> 6) & 127;
        const int r1 = (rn1 >> 6) & 127;
        #pragma unroll
        for (int nt = 0; nt < 8; nt++) {
            const int c = n0 + nt * 8 + 2 * tig + bn;
            const float2 bv = *reinterpret_cast<const float2*>(bias + c);
            const float* a = acc + (mt * 8 + nt) * 4;
            float v0 = a[0] + bv.x, v1 = a[1] + bv.y;
            float v2 = a[2] + bv.x, v3 = a[3] + bv.y;
            if (act == 1) {
                v0 = fast_gelu(v0); v1 = fast_gelu(v1);
                v2 = fast_gelu(v2); v3 = fast_gelu(v3);
            }
            if (c < ropeN) {
                int pi = ((ccol + c) & 31) >> 1;
                float inv = __expf(-(float)pi * 0.57564627324851148f);
                float s0, c0s, s1, c1s;
                __sincosf((float)r0 * inv, &s0, &c0s);
                __sincosf((float)r1 * inv, &s1, &c1s);
                float e0 = v0, od0 = v1, e1 = v2, od1 = v3;
                v0 = e0 * c0s - od0 * s0;  v1 = e0 * s0 + od0 * c0s;
                v2 = e1 * c1s - od1 * s1;  v3 = e1 * s1 + od1 * c1s;
            }
            if (Res) {
                float2 rr0 = __half22float2(*reinterpret_cast<const __half2*>(Res + q0 + c));
                float2 rr1 = __half22float2(*reinterpret_cast<const __half2*>(Res + q1 + c));
                v0 += rr0.x; v1 += rr0.y; v2 += rr1.x; v3 += rr1.y;
            }
            if (Cm) {
                *reinterpret_cast<float2*>(Cm + o0 + c) = make_float2(v0, v1);
                *reinterpret_cast<float2*>(Cm + o1 + c) = make_float2(v2, v3);
            }
            if (Ch) {
                *reinterpret_cast<uint32_t*>(Ch + o0 + c) = h2bits(v0, v1);
                *reinterpret_cast<uint32_t*>(Ch + o1 + c) = h2bits(v2, v3);
            }
        }
    }
}

// ---------------- fused GEMM + residual + LayerNorm (N = 256 = full row) ----------------
// CTA 128(M) x 256(N), 8 warps (2M x 4N), warp tile 64x64.
// v = A@W^T + bias + Res;  out = LN(v) (per full 256-wide row, stats on fp32 accumulators).
#define LA_HALFS (128 * ASTRH)                    // 5120
#define LSTAGE_HALFS (LA_HALFS + 256 * ASTRH)     // 15360
#define GEMM_LN_SMEM (STAGES * LSTAGE_HALFS * 2)  // 122880

__global__ void __launch_bounds__(256, 1) gemm_ln(
    const __half* __restrict__ A, int lda,
    const __half* __restrict__ W,
    const float* __restrict__ bias,
    const __half* __restrict__ Res,
    __half* __restrict__ preH,       // optional: pre-LN value (half)
    __half* __restrict__ outH,       // optional: LN output (half)
    float*  __restrict__ outF,       // optional: LN output (fp32)
    const float* __restrict__ gamma, const float* __restrict__ beta,
    int M, int K, int rowmap)
{
    extern __shared__ __half smh[];
    const uint32_t smb = smem_u32(smh);

    const int tid  = threadIdx.x;
    const int wid  = tid >> 5, lane = tid & 31;
    const int g    = lane >> 2, tig = lane & 3;
    const int wm   = wid & 1,  wn  = wid >> 1;
    const int m0   = wm * 64,  n0  = wn * 64;
    const int bm   = blockIdx.y * 128;
    const int nbase = maprow(bm, rowmap);

    float acc[128];
    #pragma unroll
    for (int i = 0; i < 128; i++) acc[i] = 0.f;

    const int row0 = tid >> 2, c0 = (tid & 3) * 8;
    const __half* aP = A + (size_t)(nbase + row0) * lda + c0;
    const __half* bP = W + (size_t)row0 * K + c0;
    const uint32_t aD0 = (uint32_t)(row0 * ASTRH + c0) * 2;
    const uint32_t bD0 = (uint32_t)(LA_HALFS + row0 * ASTRH + c0) * 2;
    const size_t aStride = (size_t)64 * lda;
    const size_t bStride = (size_t)64 * K;

    uint32_t aB[4], bB[4];
    #pragma unroll
    for (int mt = 0; mt < 4; mt++)
        aB[mt] = smb + (uint32_t)((m0 + mt * 16 + (lane & 15)) * ASTRH + (lane >> 4) * 8) * 2;
    #pragma unroll
    for (int p = 0; p < 4; p++)
        bB[p] = smb + (uint32_t)(LA_HALFS
                 + (n0 + p * 16 + (lane & 7) + ((lane >> 4) & 1) * 8) * ASTRH
                 + ((lane >> 3) & 1) * 8) * 2;

    const int nk = K / BKK;

    #pragma unroll
    for (int s = 0; s < STAGES - 1; s++) {
        uint32_t sb = smb + s * (LSTAGE_HALFS * 2);
        int k0 = s * BKK;
        #pragma unroll
        for (int t = 0; t < 2; t++) cp_async16(sb + aD0 + t * (64 * ASTRH * 2), aP + t * aStride + k0);
        #pragma unroll
        for (int t = 0; t < 4; t++) cp_async16(sb + bD0 + t * (64 * ASTRH * 2), bP + t * bStride + k0);
        CP_COMMIT();
    }

    for (int i = 0; i < nk; i++) {
        CP_WAIT(STAGES - 2);
        __syncthreads();
        {
            int k0 = (i + STAGES - 1) * BKK;
            if (k0 < K) {
                int st = (i + STAGES - 1) % STAGES;
                uint32_t sb = smb + st * (LSTAGE_HALFS * 2);
                #pragma unroll
                for (int t = 0; t < 2; t++) cp_async16(sb + aD0 + t * (64 * ASTRH * 2), aP + t * aStride + k0);
                #pragma unroll
                for (int t = 0; t < 4; t++) cp_async16(sb + bD0 + t * (64 * ASTRH * 2), bP + t * bStride + k0);
            }
            CP_COMMIT();
        }
        const uint32_t stOff = (i % STAGES) * (LSTAGE_HALFS * 2);
        #pragma unroll
        for (int k16 = 0; k16 < 2; k16++) {
            const uint32_t kOff = stOff + k16 * 32;
            uint32_t af[4][4], bf[8][2];
            #pragma unroll
            for (int mt = 0; mt < 4; mt++)
                ldsm4(af[mt], aB[mt] + kOff);
            #pragma unroll
            for (int p = 0; p < 4; p++) {
                uint32_t r[4];
                ldsm4(r, bB[p] + kOff);
                bf[2 * p][0] = r[0]; bf[2 * p][1] = r[1];
                bf[2 * p + 1][0] = r[2]; bf[2 * p + 1][1] = r[3];
            }
            #pragma unroll
            for (int mt = 0; mt < 4; mt++)
                #pragma unroll
                for (int nt = 0; nt < 8; nt++)
                    mma_f16(acc + (mt * 8 + nt) * 4, af[mt], bf[nt]);
        }
    }

    // ---------------- fused epilogue: bias + residual, then LN over full rows ----------------
    __syncthreads();                               // all warps done with stage smem
    float* Red = reinterpret_cast<float*>(smh);    // [4 wn][128 rows][2] = 4 KB

    // pass 1: v = acc + bias + Res; accumulate per-row partial sums
    #pragma unroll
    for (int mt = 0; mt < 4; mt++) {
        const int lr0 = m0 + mt * 16 + g, lr1 = lr0 + 8;
        const size_t q0 = (size_t)(nbase + lr0) * 256;
        const size_t q1 = (size_t)(nbase + lr1) * 256;
        float s0 = 0.f, sq0 = 0.f, s1 = 0.f, sq1 = 0.f;
        #pragma unroll
        for (int nt = 0; nt < 8; nt++) {
            const int c = n0 + nt * 8 + 2 * tig;
            const float2 bv = *reinterpret_cast<const float2*>(bias + c);
            float* a = acc + (mt * 8 + nt) * 4;
            float2 rr0 = __half22float2(*reinterpret_cast<const __half2*>(Res + q0 + c));
            float2 rr1 = __half22float2(*reinterpret_cast<const __half2*>(Res + q1 + c));
            float v0 = a[0] + bv.x + rr0.x, v1 = a[1] + bv.y + rr0.y;
            float v2 = a[2] + bv.x + rr1.x, v3 = a[3] + bv.y + rr1.y;
            a[0] = v0; a[1] = v1; a[2] = v2; a[3] = v3;
            s0 += v0 + v1;  sq0 += v0 * v0 + v1 * v1;
            s1 += v2 + v3;  sq1 += v2 * v2 + v3 * v3;
        }
        // reduce over tig lanes (xor 1, 2) — same g shares row
        #pragma unroll
        for (int o = 1; o <= 2; o <<= 1) {
            s0  += __shfl_xor_sync(0xffffffffu, s0,  o);
            sq0 += __shfl_xor_sync(0xffffffffu, sq0, o);
            s1  += __shfl_xor_sync(0xffffffffu, s1,  o);
            sq1 += __shfl_xor_sync(0xffffffffu, sq1, o);
        }
        if (tig == 0) {
            Red[(wn * 128 + lr0) * 2 + 0] = s0;
            Red[(wn * 128 + lr0) * 2 + 1] = sq0;
            Red[(wn * 128 + lr1) * 2 + 0] = s1;
            Red[(wn * 128 + lr1) * 2 + 1] = sq1;
        }
    }
    __syncthreads();

    // pass 2: finalize stats, normalize, write
    #pragma unroll
    for (int mt = 0; mt < 4; mt++) {
        const int lr0 = m0 + mt * 16 + g, lr1 = lr0 + 8;
        const size_t o0 = (size_t)(nbase + lr0) * 256;
        const size_t o1 = (size_t)(nbase + lr1) * 256;
        float sum0 = 0.f, sq0 = 0.f, sum1 = 0.f, sq1 = 0.f;
        #pragma unroll
        for (int w = 0; w < 4; w++) {
            sum0 += Red[(w * 128 + lr0) * 2 + 0];
            sq0  += Red[(w * 128 + lr0) * 2 + 1];
            sum1 += Red[(w * 128 + lr1) * 2 + 0];
            sq1  += Red[(w * 128 + lr1) * 2 + 1];
        }
        const float mean0 = sum0 * (1.0f / 256.0f);
        const float mean1 = sum1 * (1.0f / 256.0f);
        const float inv0 = rsqrtf(fmaxf(sq0 * (1.0f / 256.0f) - mean0 * mean0, 0.f) + 1e-5f);
        const float inv1 = rsqrtf(fmaxf(sq1 * (1.0f / 256.0f) - mean1 * mean1, 0.f) + 1e-5f);
        #pragma unroll
        for (int nt = 0; nt < 8; nt++) {
            const int c = n0 + nt * 8 + 2 * tig;
            const float* a = acc + (mt * 8 + nt) * 4;
            if (preH) {
                *reinterpret_cast<uint32_t*>(preH + o0 + c) = h2bits(a[0], a[1]);
                *reinterpret_cast<uint32_t*>(preH + o1 + c) = h2bits(a[2], a[3]);
            }
            const float2 gg = *reinterpret_cast<const float2*>(gamma + c);
            const float2 bb = *reinterpret_cast<const float2*>(beta + c);
            float y0 = (a[0] - mean0) * inv0 * gg.x + bb.x;
            float y1 = (a[1] - mean0) * inv0 * gg.y + bb.y;
            float y2 = (a[2] - mean1) * inv1 * gg.x + bb.x;
            float y3 = (a[3] - mean1) * inv1 * gg.y + bb.y;
            if (outH) {
                *reinterpret_cast<uint32_t*>(outH + o0 + c) = h2bits(y0, y1);
                *reinterpret_cast<uint32_t*>(outH + o1 + c) = h2bits(y2, y3);
            }
            if (outF) {
                *reinterpret_cast<float2*>(outF + o0 + c) = make_float2(y0, y1);
                *reinterpret_cast<float2*>(outF + o1 + c) = make_float2(y2, y3);
            }
        }
    }
}

// ---------------- float -> half conversion ----------------
__global__ void f2h_kernel(const float4* __restrict__ in, uint4* __restrict__ out, int n8) {
    int i = blockIdx.x * blockDim.x + threadIdx.x;
    if (i >= n8) return;
    float4 a = in[2 * i], b = in[2 * i + 1];
    uint4 o;
    o.x = h2bits(a.x, a.y);
    o.y = h2bits(a.z, a.w);
    o.z = h2bits(b.x, b.y);
    o.w = h2bits(b.z, b.w);
    out[i] = o;
}

__global__ void f2h_weights(const float4* yinw, const float4* youtw, const float4* xinw,
                            const float4* xoutw, const float4* w1, const float4* w2,
                            uint4* dst) {
    int i = blockIdx.x * blockDim.x + threadIdx.x;
    const float4* src; int l;
    if      (i < 24576)  { src = yinw;  l = i; }
    else if (i < 32768)  { src = youtw; l = i - 24576; }
    else if (i < 57344)  { src = xinw;  l = i - 32768; }
    else if (i < 65536)  { src = xoutw; l = i - 57344; }
    else if (i < 98304)  { src = w1;    l = i - 65536; }
    else                 { src = w2;    l = i - 98304; }
    float4 a = src[2 * l], b = src[2 * l + 1];
    uint4 o;
    o.x = h2bits(a.x, a.y);
    o.y = h2bits(a.z, a.w);
    o.z = h2bits(b.x, b.y);
    o.w = h2bits(b.z, b.w);
    dst[i] = o;
}

// ---------------- tensor-core attention (frozen R13) ----------------
template<int LQ, int LK, int MODEB>
__global__ void attn_mma(
    const __half* __restrict__ qkv, __half* __restrict__ out,
    const int* __restrict__ mask, int q_r0)
{
    constexpr int NW  = LQ / 16;
    constexpr int NJ  = LK / 8;
    constexpr int NT2 = LK / 16;
    constexpr int THREADS = NW * 32;
    constexpr int STR = 40;

    const int seq = blockIdx.x, head = blockIdx.y;
    int base, pstride;
    if (MODEB) { base = (seq >> 6) * 8192 + (seq & 63); pstride = 64; }
    else       { base = seq * 64;                        pstride = 1;  }

    __shared__ __half Qs[LQ * STR];
    __shared__ __half Ks[LK * STR];
    __shared__ __half Vs[LK * STR];
    __shared__ float Bias[LK];

    const int tid = threadIdx.x, wid = tid >> 5, lane = tid & 31;
    const int qoff = head * 32, koff = 256 + head * 32, voff = 512 + head * 32;

    for (int idx = tid; idx < LQ * 4; idx += THREADS) {
        int r = idx >> 2, c = idx & 3;
        *reinterpret_cast<uint4*>(&Qs[r * STR + c * 8]) =
            *reinterpret_cast<const uint4*>(qkv + (size_t)(base + (q_r0 + r) * pstride) * 768 + qoff + c * 8);
    }
    for (int idx = tid; idx < LK * 4; idx += THREADS) {
        int r = idx >> 2, c = idx & 3;
        size_t rn = (size_t)(base + r * pstride) * 768;
        *reinterpret_cast<uint4*>(&Ks[r * STR + c * 8]) =
            *reinterpret_cast<const uint4*>(qkv + rn + koff + c * 8);
        *reinterpret_cast<uint4*>(&Vs[r * STR + c * 8]) =
            *reinterpret_cast<const uint4*>(qkv + rn + voff + c * 8);
    }
    for (int idx = tid; idx < LK; idx += THREADS) {
        float bv = 0.f;
        if (MODEB) { int b = seq >> 6; if (mask[b * 128 + idx] == 0) bv = -1e9f; }
        Bias[idx] = bv;
    }
    __syncthreads();

    const uint32_t smbQ = smem_u32(Qs), smbK = smem_u32(Ks), smbV = smem_u32(Vs);

    uint32_t aQ[2][4];
    {
        uint32_t addr = smbQ + (uint32_t)((wid * 16 + (lane & 15)) * STR + (lane >> 4) * 8) * 2;
        ldsm4(aQ[0], addr);
        ldsm4(aQ[1], addr + 32);
    }

    float sacc[NJ][4];
    #pragma unroll
    for (int j = 0; j < NJ; j++)
        #pragma unroll
        for (int t = 0; t < 4; t++) sacc[j][t] = 0.f;

    #pragma unroll
    for (int p = 0; p < NJ / 2; p++) {
        uint32_t addr = smbK + (uint32_t)((p * 16 + (lane & 7) + ((lane >> 4) & 1) * 8) * STR
                                          + ((lane >> 3) & 1) * 8) * 2;
        uint32_t r0[4], r1[4];
        ldsm4(r0, addr);
        ldsm4(r1, addr + 32);
        { uint32_t b[2] = {r0[0], r0[1]}; mma_f16(sacc[2 * p],     aQ[0], b); }
        { uint32_t b[2] = {r1[0], r1[1]}; mma_f16(sacc[2 * p],     aQ[1], b); }
        { uint32_t b[2] = {r0[2], r0[3]}; mma_f16(sacc[2 * p + 1], aQ[0], b); }
        { uint32_t b[2] = {r1[2], r1[3]}; mma_f16(sacc[2 * p + 1], aQ[1], b); }
    }

    const float scale = 0.17677669529663689f;
    float mx0 = -3.4e38f, mx1 = -3.4e38f;
    #pragma unroll
    for (int j = 0; j < NJ; j++) {
        int col = j * 8 + 2 * (lane & 3);
        float b0 = Bias[col], b1 = Bias[col + 1];
        sacc[j][0] = fmaf(sacc[j][0], scale, b0);
        sacc[j][1] = fmaf(sacc[j][1], scale, b1);
        sacc[j][2] = fmaf(sacc[j][2], scale, b0);
        sacc[j][3] = fmaf(sacc[j][3], scale, b1);
        mx0 = fmaxf(mx0, fmaxf(sacc[j][0], sacc[j][1]));
        mx1 = fmaxf(mx1, fmaxf(sacc[j][2], sacc[j][3]));
    }
    mx0 = fmaxf(mx0, __shfl_xor_sync(0xffffffffu, mx0, 1));
    mx0 = fmaxf(mx0, __shfl_xor_sync(0xffffffffu, mx0, 2));
    mx1 = fmaxf(mx1, __shfl_xor_sync(0xffffffffu, mx1, 1));
    mx1 = fmaxf(mx1, __shfl_xor_sync(0xffffffffu, mx1, 2));
    float sum0 = 0.f, sum1 = 0.f;
    #pragma unroll
    for (int j = 0; j < NJ; j++) {
        float p0 = __expf(sacc[j][0] - mx0);
        float p1 = __expf(sacc[j][1] - mx0);
        float p2 = __expf(sacc[j][2] - mx1);
        float p3 = __expf(sacc[j][3] - mx1);
        sacc[j][0] = p0; sacc[j][1] = p1; sacc[j][2] = p2; sacc[j][3] = p3;
        sum0 += p0 + p1; sum1 += p2 + p3;
    }
    sum0 += __shfl_xor_sync(0xffffffffu, sum0, 1);
    sum0 += __shfl_xor_sync(0xffffffffu, sum0, 2);
    sum1 += __shfl_xor_sync(0xffffffffu, sum1, 1);
    sum1 += __shfl_xor_sync(0xffffffffu, sum1, 2);
    const float inv0 = 1.f / sum0, inv1 = 1.f / sum1;

    uint32_t aP[NT2][4];
    #pragma unroll
    for (int t = 0; t < NT2; t++) {
        aP[t][0] = h2bits(sacc[2 * t][0],     sacc[2 * t][1]);
        aP[t][1] = h2bits(sacc[2 * t][2],     sacc[2 * t][3]);
        aP[t][2] = h2bits(sacc[2 * t + 1][0], sacc[2 * t + 1][1]);
        aP[t][3] = h2bits(sacc[2 * t + 1][2], sacc[2 * t + 1][3]);
    }

    float oacc[4][4];
    #pragma unroll
    for (int n = 0; n < 4; n++)
        #pragma unroll
        for (int t = 0; t < 4; t++) oacc[n][t] = 0.f;

    #pragma unroll
    for (int t = 0; t < NT2; t++) {
        uint32_t addr = smbV + (uint32_t)((16 * t + (lane & 15)) * STR + (lane >> 4) * 8) * 2;
        uint32_t v0[4], v1[4];
        ldsm4t(v0, addr);
        ldsm4t(v1, addr + 32);
        { uint32_t b[2] = {v0[0], v0[1]}; mma_f16(oacc[0], aP[t], b); }
        { uint32_t b[2] = {v0[2], v0[3]}; mma_f16(oacc[1], aP[t], b); }
        { uint32_t b[2] = {v1[0], v1[1]}; mma_f16(oacc[2], aP[t], b); }
        { uint32_t b[2] = {v1[2], v1[3]}; mma_f16(oacc[3], aP[t], b); }
    }

    const int r0 = 16 * wid + (lane >> 2);
    const int r1 = r0 + 8;
    const size_t o0 = (size_t)(base + (q_r0 + r0) * pstride) * 256 + head * 32;
    const size_t o1 = (size_t)(base + (q_r0 + r1) * pstride) * 256 + head * 32;
    #pragma unroll
    for (int nc = 0; nc < 4; nc++) {
        const int col = nc * 8 + 2 * (lane & 3);
        *reinterpret_cast<uint32_t*>(out + o0 + col) = h2bits(oacc[nc][0] * inv0, oacc[nc][1] * inv0);
        *reinterpret_cast<uint32_t*>(out + o1 + col) = h2bits(oacc[nc][2] * inv1, oacc[nc][3] * inv1);
    }
}

// ---------------- launcher ----------------
extern "C" void kernel_launch(void* const* d_in, const int* in_sizes, int n_in,
                              void* d_out, int out_size) {
    const float* src  = (const float*)d_in[0];
    const int*   mask = (const int*)  d_in[1];
    int wi = 2;
    if (n_in > 2 && in_sizes[2] == 1) wi = 3;
    const float* y_in_w  = (const float*)d_in[wi + 0];
    const float* y_in_b  = (const float*)d_in[wi + 1];
    const float* y_out_w = (const float*)d_in[wi + 2];
    const float* y_out_b = (const float*)d_in[wi + 3];
    const float* x_in_w  = (const float*)d_in[wi + 4];
    const float* x_in_b  = (const float*)d_in[wi + 5];
    const float* x_out_w = (const float*)d_in[wi + 6];
    const float* x_out_b = (const float*)d_in[wi + 7];
    const float* w1      = (const float*)d_in[wi + 8];
    const float* b1      = (const float*)d_in[wi + 9];
    const float* w2      = (const float*)d_in[wi + 10];
    const float* b2      = (const float*)d_in[wi + 11];
    const float* n1_g    = (const float*)d_in[wi + 12];
    const float* n1_b    = (const float*)d_in[wi + 13];
    const float* n2_g    = (const float*)d_in[wi + 14];
    const float* n2_b    = (const float*)d_in[wi + 15];
    const float* n3_g    = (const float*)d_in[wi + 16];
    const float* n3_b    = (const float*)d_in[wi + 17];

    __half *QKVh, *ATTh, *Xnh, *X2h, *X2nh, *Hmh, *srch, *Wh;
    cudaGetSymbolAddress((void**)&QKVh, g_QKVh);
    cudaGetSymbolAddress((void**)&ATTh, g_ATTh);
    cudaGetSymbolAddress((void**)&Xnh,  g_Xnh);
    cudaGetSymbolAddress((void**)&X2h,  g_X2h);
    cudaGetSymbolAddress((void**)&X2nh, g_X2nh);
    cudaGetSymbolAddress((void**)&Hmh,  g_Hmh);
    cudaGetSymbolAddress((void**)&srch, g_srch);
    cudaGetSymbolAddress((void**)&Wh,   g_Wh);

    cudaFuncSetAttribute(gemm_mma, cudaFuncAttributeMaxDynamicSharedMemorySize, GEMM_SMEM);
    cudaFuncSetAttribute(gemm_ln,  cudaFuncAttributeMaxDynamicSharedMemorySize, GEMM_LN_SMEM);

    // ---- conversions ----
    f2h_kernel<<<(NT * EE / 8 + 255) / 256, 256>>>((const float4*)src, (uint4*)srch, NT * EE / 8);
    f2h_weights<<<512, 256>>>((const float4*)y_in_w, (const float4*)y_out_w,
                              (const float4*)x_in_w, (const float4*)x_out_w,
                              (const float4*)w1, (const float4*)w2, (uint4*)Wh);

    // ---- stage A ----
    gemm_mma<<<dim3(6, 512), 128, GEMM_SMEM>>>(srch, 256, Wh + WOFF_YIN, y_in_b, nullptr, 0,
                                               nullptr, QKVh, 768, 0, NT, 768, 256, 0, 0, 0);
    attn_mma<64, 64, 0><<<dim3(1024, HH), 128>>>(QKVh, ATTh, nullptr, 0);
    // y_out + residual(src) + LN1 -> Xnh
    gemm_ln<<<dim3(1, 512), 256, GEMM_LN_SMEM>>>(ATTh, 256, Wh + WOFF_YOUT, y_out_b, srch,
                                                 nullptr, Xnh, nullptr, n1_g, n1_b,
                                                 NT, 256, 0);

    // ---- stage B ----
    gemm_mma<<<dim3(6, 384), 128, GEMM_SMEM>>>(Xnh, 256, Wh + WOFF_XIN, x_in_b, nullptr, 0,
                                               nullptr, QKVh, 768, 0, 49152, 768, 256, 1, 0, 512);
    gemm_mma<<<dim3(2, 128), 128, GEMM_SMEM>>>(Xnh, 256, Wh + WOFF_XIN, x_in_b, nullptr, 0,
                                               nullptr, QKVh, 768, 0, 16384, 256, 256, 2, 0, 256);
    attn_mma<96, 96, 1><<<dim3(512, HH), 192>>>(QKVh, ATTh, mask, 0);
    // xout_ctx + residual(Xnh) ; pre-LN -> X2h (kv recompute input), LN2 -> X2nh
    gemm_ln<<<dim3(1, 384), 256, GEMM_LN_SMEM>>>(ATTh, 256, Wh + WOFF_XOUT, x_out_b, Xnh,
                                                 X2h, X2nh, nullptr, n2_g, n2_b,
                                                 49152, 256, 1);
    gemm_mma<<<dim3(4, 384), 128, GEMM_SMEM>>>(X2h, 256, Wh + WOFF_XIN + 65536, x_in_b + 256,
                                               nullptr, 0, nullptr, QKVh, 768, 256,
                                               49152, 512, 256, 1, 0, 256);
    attn_mma<32, 96, 1><<<dim3(512, HH), 64>>>(QKVh, ATTh, mask, 96);
    // xout_qry + residual(Xnh) + LN2 -> X2nh
    gemm_ln<<<dim3(1, 128), 256, GEMM_LN_SMEM>>>(ATTh, 256, Wh + WOFF_XOUT, x_out_b, Xnh,
                                                 nullptr, X2nh, nullptr, n2_g, n2_b,
                                                 16384, 256, 2);

    // ---- MLP + final LN ----
    gemm_mma<<<dim3(8, 512), 128, GEMM_SMEM>>>(X2nh, 256, Wh + WOFF_W1, b1, nullptr, 0,
                                               nullptr, Hmh, 1024, 0, NT, 1024, 256, 0, 1, 0);
    // w2 + residual(X2nh) + LN3 -> d_out (fp32)
    gemm_ln<<<dim3(1, 512), 256, GEMM_LN_SMEM>>>(Hmh, 1024, Wh + WOFF_W2, b2, X2nh,
                                                 nullptr, nullptr, (float*)d_out, n3_g, n3_b,
                                                 NT, 1024, 0);
}